// round 6
// baseline (speedup 1.0000x reference)
#include <cuda_runtime.h>
#include <cuda_bf16.h>
#include <math.h>

#define N_NODES 40000
#define E_EDGES 640000
#define F       128
#define HD      128
#define NHEADS  4
#define VOCABV  64

// packed fp32x2 helpers (sm_100a+)
#define FMA2(d, a, b, c) \
    asm("fma.rn.f32x2 %0, %1, %2, %3;" : "=l"(d) : "l"(a), "l"(b), "l"(c))
#define PACK_DUP(d, f) \
    asm("mov.b64 %0, {%1, %1};" : "=l"(d) : "f"(f))
#define UNPACK2(lo, hi, d) \
    asm("mov.b64 {%0, %1}, %2;" : "=f"(lo), "=f"(hi) : "l"(d))

// ---------------- scratch ----------------
__device__ unsigned g_xh [N_NODES * F / 2];   // bf16 hi pairs of x_y
__device__ unsigned g_xl [N_NODES * F / 2];   // bf16 lo pairs
__device__ float g_q   [N_NODES * HD];
__device__ float g_k   [N_NODES * HD];
__device__ float g_v   [N_NODES * HD];
__device__ float g_skip[N_NODES * HD];
__device__ float g_feat[N_NODES * HD];        // final per-node feature (msg/den + skip)
__device__ int   g_cnt [N_NODES];             // per-dst degree
__device__ int   g_start[N_NODES + 1];        // CSR offsets
__device__ int   g_cur [N_NODES];             // scatter cursors
__device__ int   g_sorted[E_EDGES];           // src ids grouped by dst

__device__ __forceinline__ unsigned pack_bf16(float lo, float hi) {
    unsigned r;
    asm("cvt.rn.bf16x2.f32 %0, %1, %2;" : "=r"(r) : "f"(hi), "f"(lo));
    return r;
}

__device__ __forceinline__ void mma_bf16(float* d, const unsigned* a, const unsigned* b) {
    asm("mma.sync.aligned.m16n8k16.row.col.f32.bf16.bf16.f32 "
        "{%0,%1,%2,%3}, {%4,%5,%6,%7}, {%8,%9}, {%0,%1,%2,%3};"
        : "+f"(d[0]), "+f"(d[1]), "+f"(d[2]), "+f"(d[3])
        : "r"(a[0]), "r"(a[1]), "r"(a[2]), "r"(a[3]), "r"(b[0]), "r"(b[1]));
}

// ---------------- K0: x_y = x + emb[y], split to bf16 hi/lo ----------------
__global__ void k_xy(const float* __restrict__ x,
                     const int* __restrict__ y,
                     const float* __restrict__ emb) {
    int i = blockIdx.x * blockDim.x + threadIdx.x;
    if (i >= N_NODES * (F / 4)) return;
    int n  = i >> 5;
    int f4 = i & 31;
    int yv = y[n];
    float4 xv = ((const float4*)x)[i];
    float4 ev = *((const float4*)(emb + yv * F) + f4);
    float r[4] = { xv.x + ev.x, xv.y + ev.y, xv.z + ev.z, xv.w + ev.w };
    unsigned h[2], l[2];
    #pragma unroll
    for (int p = 0; p < 2; p++) {
        float a = r[2 * p], b = r[2 * p + 1];
        float ha = __bfloat162float(__float2bfloat16_rn(a));
        float hb = __bfloat162float(__float2bfloat16_rn(b));
        h[p] = pack_bf16(ha, hb);
        l[p] = pack_bf16(a - ha, b - hb);
    }
    ((uint2*)g_xh)[i] = make_uint2(h[0], h[1]);
    ((uint2*)g_xl)[i] = make_uint2(l[0], l[1]);
}

// ---------------- zero degree counters ----------------
__global__ void k_zero() {
    int i = blockIdx.x * blockDim.x + threadIdx.x;
    if (i < N_NODES / 4) ((int4*)g_cnt)[i] = make_int4(0, 0, 0, 0);
}

// ---------------- CSR pass 1: histogram of dst ----------------
__global__ void k_hist(const int* __restrict__ ei) {
    int i = blockIdx.x * blockDim.x + threadIdx.x;
    if (i < E_EDGES) atomicAdd(&g_cnt[ei[E_EDGES + i]], 1);
}

// ---------------- CSR pass 2: exclusive scan (single block) ----------------
__global__ void __launch_bounds__(1024)
k_scan() {
    __shared__ int ps[1024];
    int tid  = threadIdx.x;
    int base = tid * 40;                    // 1024*40 = 40960 >= N
    int s = 0;
    for (int i = 0; i < 40; i++) {
        int idx = base + i;
        if (idx < N_NODES) s += g_cnt[idx];
    }
    ps[tid] = s;
    __syncthreads();
    for (int d = 1; d < 1024; d <<= 1) {    // Hillis-Steele inclusive scan
        int v = (tid >= d) ? ps[tid - d] : 0;
        __syncthreads();
        ps[tid] += v;
        __syncthreads();
    }
    int run = (tid == 0) ? 0 : ps[tid - 1];
    for (int i = 0; i < 40; i++) {
        int idx = base + i;
        if (idx < N_NODES) {
            g_start[idx] = run;
            g_cur[idx]   = run;
            run += g_cnt[idx];
        }
    }
    if (tid == 0) g_start[N_NODES] = E_EDGES;
}

// ---------------- CSR pass 3: scatter src grouped by dst ----------------
__global__ void k_scatter(const int* __restrict__ ei) {
    int i = blockIdx.x * blockDim.x + threadIdx.x;
    if (i >= E_EDGES) return;
    int src = ei[i];
    int dst = ei[E_EDGES + i];
    int pos = atomicAdd(&g_cur[dst], 1);
    g_sorted[pos] = src;
}

// ---------------- K1: tensor-core projection GEMM (bf16 3-term split) --------
__global__ void __launch_bounds__(256, 2)
k_proj(const float* __restrict__ Wq, const float* __restrict__ bq,
       const float* __restrict__ Wk, const float* __restrict__ bk,
       const float* __restrict__ Wv, const float* __restrict__ bv,
       const float* __restrict__ Ws, const float* __restrict__ bs) {
    const float* W; const float* bias; float* out;
    switch (blockIdx.y) {
        case 0:  W = Wq; bias = bq; out = g_q;    break;
        case 1:  W = Wk; bias = bk; out = g_k;    break;
        case 2:  W = Wv; bias = bv; out = g_v;    break;
        default: W = Ws; bias = bs; out = g_skip; break;
    }
    __shared__ unsigned Ah[128 * 9], Al[128 * 9], Bh[128 * 9], Bl[128 * 9];

    int tid  = threadIdx.x;
    int wid  = tid >> 5, lane = tid & 31;
    int wm   = wid >> 1;
    int wn   = wid & 1;
    int g    = lane >> 2;
    int tig  = lane & 3;
    int m0   = blockIdx.x * 128;

    float C[2][8][4];
    #pragma unroll
    for (int mt = 0; mt < 2; mt++)
        #pragma unroll
        for (int nt = 0; nt < 8; nt++)
            #pragma unroll
            for (int c = 0; c < 4; c++) C[mt][nt][c] = 0.f;

    for (int kc = 0; kc < 128; kc += 16) {
        #pragma unroll
        for (int t = 0; t < 4; t++) {
            int idx = tid + t * 256;
            int row = idx >> 3, kp = idx & 7;
            int gr  = m0 + row;
            unsigned vh = 0u, vl = 0u;
            if (gr < N_NODES) {
                int src = gr * 64 + (kc >> 1) + kp;
                vh = g_xh[src];
                vl = g_xl[src];
            }
            Ah[row * 9 + kp] = vh;
            Al[row * 9 + kp] = vl;
        }
        #pragma unroll
        for (int t = 0; t < 4; t++) {
            int idx = tid + t * 256;
            int n  = idx & 127, kp = idx >> 7;
            float w0 = W[(kc + 2 * kp)     * 128 + n];
            float w1 = W[(kc + 2 * kp + 1) * 128 + n];
            float h0 = __bfloat162float(__float2bfloat16_rn(w0));
            float h1 = __bfloat162float(__float2bfloat16_rn(w1));
            Bh[n * 9 + kp] = pack_bf16(h0, h1);
            Bl[n * 9 + kp] = pack_bf16(w0 - h0, w1 - h1);
        }
        __syncthreads();

        unsigned ah[2][4], al[2][4];
        #pragma unroll
        for (int mt = 0; mt < 2; mt++) {
            int base = wm * 32 + mt * 16;
            ah[mt][0] = Ah[(base + g)     * 9 + tig];
            ah[mt][1] = Ah[(base + g + 8) * 9 + tig];
            ah[mt][2] = Ah[(base + g)     * 9 + tig + 4];
            ah[mt][3] = Ah[(base + g + 8) * 9 + tig + 4];
            al[mt][0] = Al[(base + g)     * 9 + tig];
            al[mt][1] = Al[(base + g + 8) * 9 + tig];
            al[mt][2] = Al[(base + g)     * 9 + tig + 4];
            al[mt][3] = Al[(base + g + 8) * 9 + tig + 4];
        }
        #pragma unroll
        for (int nt = 0; nt < 8; nt++) {
            int nb = wn * 64 + nt * 8;
            unsigned bh[2] = { Bh[(nb + g) * 9 + tig], Bh[(nb + g) * 9 + tig + 4] };
            unsigned bl[2] = { Bl[(nb + g) * 9 + tig], Bl[(nb + g) * 9 + tig + 4] };
            #pragma unroll
            for (int mt = 0; mt < 2; mt++) {
                mma_bf16(C[mt][nt], ah[mt], bh);
                mma_bf16(C[mt][nt], ah[mt], bl);
                mma_bf16(C[mt][nt], al[mt], bh);
            }
        }
        __syncthreads();
    }

    #pragma unroll
    for (int nt = 0; nt < 8; nt++) {
        int col = wn * 64 + nt * 8 + 2 * tig;
        float2 b2 = *(const float2*)(bias + col);
        #pragma unroll
        for (int mt = 0; mt < 2; mt++) {
            int r0 = m0 + wm * 32 + mt * 16 + g;
            int r1 = r0 + 8;
            if (r0 < N_NODES)
                *(float2*)(out + r0 * 128 + col) =
                    make_float2(C[mt][nt][0] + b2.x, C[mt][nt][1] + b2.y);
            if (r1 < N_NODES)
                *(float2*)(out + r1 * 128 + col) =
                    make_float2(C[mt][nt][2] + b2.x, C[mt][nt][3] + b2.y);
        }
    }
}

// ---------------- K2: CSR aggregation, warp per dst node ----------------
// For node n: loop over its incoming edges; accumulate ea and ea*v in regs.
// Epilogue: feat = acc/den + skip (den==0 -> skip only). No atomics.
__global__ void __launch_bounds__(256)
k_agg(void) {
    int n    = blockIdx.x * 8 + (threadIdx.x >> 5);
    int lane = threadIdx.x & 31;
    if (n >= N_NODES) return;
    int s0 = g_start[n];
    int s1 = g_start[n + 1];

    float4 qv = *(const float4*)(g_q + n * 128 + lane * 4);
    float4 acc = make_float4(0.f, 0.f, 0.f, 0.f);
    float den = 0.f;

    // 1-deep software pipeline over the segment
    int e = s0;
    float4 kn, vn;
    if (e < s1) {
        int s = g_sorted[e];
        kn = *(const float4*)(g_k + s * 128 + lane * 4);
        vn = *(const float4*)(g_v + s * 128 + lane * 4);
    }
    while (e < s1) {
        float4 kc = kn, vc = vn;
        int en = e + 1;
        if (en < s1) {
            int s = g_sorted[en];
            kn = *(const float4*)(g_k + s * 128 + lane * 4);
            vn = *(const float4*)(g_v + s * 128 + lane * 4);
        }
        float sdot = qv.x * kc.x + qv.y * kc.y + qv.z * kc.z + qv.w * kc.w;
        sdot += __shfl_xor_sync(0xffffffffu, sdot, 1);
        sdot += __shfl_xor_sync(0xffffffffu, sdot, 2);
        sdot += __shfl_xor_sync(0xffffffffu, sdot, 4);
        float ea = __expf(sdot * 0.17677669529663687f);   // 1/sqrt(32)
        den += ea;
        acc.x = fmaf(ea, vc.x, acc.x);
        acc.y = fmaf(ea, vc.y, acc.y);
        acc.z = fmaf(ea, vc.z, acc.z);
        acc.w = fmaf(ea, vc.w, acc.w);
        e = en;
    }
    float inv = (den > 0.f) ? (1.0f / den) : 0.f;
    float4 sk = *(const float4*)(g_skip + n * 128 + lane * 4);
    float4 ft = make_float4(fmaf(acc.x, inv, sk.x), fmaf(acc.y, inv, sk.y),
                            fmaf(acc.z, inv, sk.z), fmaf(acc.w, inv, sk.w));
    *(float4*)(g_feat + n * 128 + lane * 4) = ft;
}

// ---------------- K3: classifier out = g_feat @ Wl + bl, f32x2 ----------------
__global__ void __launch_bounds__(128, 4)
k_cls(const float* __restrict__ Wl, const float* __restrict__ bl,
      float* __restrict__ out) {
    __shared__ float As[16][132];
    __shared__ float Bs[16][68];
    int tid = threadIdx.x;
    int m0  = blockIdx.x * 128;
    int ty  = tid >> 3;
    int tx  = tid & 7;

    unsigned long long acc2[8][4];
    #pragma unroll
    for (int i = 0; i < 8; i++)
        #pragma unroll
        for (int j = 0; j < 4; j++) acc2[i][j] = 0ULL;

    for (int kc = 0; kc < 128; kc += 16) {
        #pragma unroll
        for (int it = 0; it < 4; it++) {
            int j   = tid + it * 128;
            int row = j >> 2;
            int k4  = j & 3;
            int gr  = m0 + row;
            float4 av = make_float4(0.f, 0.f, 0.f, 0.f);
            if (gr < N_NODES)
                av = *(const float4*)(g_feat + gr * 128 + kc + k4 * 4);
            As[k4 * 4 + 0][row] = av.x;
            As[k4 * 4 + 1][row] = av.y;
            As[k4 * 4 + 2][row] = av.z;
            As[k4 * 4 + 3][row] = av.w;
        }
        #pragma unroll
        for (int it = 0; it < 2; it++) {
            int j  = tid + it * 128;
            int kk = j >> 4;
            int n4 = j & 15;
            float4 wv = *(const float4*)(Wl + (kc + kk) * 64 + n4 * 4);
            *(float4*)(&Bs[kk][n4 * 4]) = wv;
        }
        __syncthreads();
        #pragma unroll
        for (int k = 0; k < 16; k++) {
            float a[8];
            *(float4*)(a)     = *(const float4*)(&As[k][ty * 8]);
            *(float4*)(a + 4) = *(const float4*)(&As[k][ty * 8 + 4]);
            unsigned long long b2[4];
            #pragma unroll
            for (int j = 0; j < 4; j++)
                b2[j] = *(const unsigned long long*)(&Bs[k][tx * 8 + j * 2]);
            #pragma unroll
            for (int i = 0; i < 8; i++) {
                unsigned long long av;
                PACK_DUP(av, a[i]);
                #pragma unroll
                for (int j = 0; j < 4; j++)
                    FMA2(acc2[i][j], av, b2[j], acc2[i][j]);
            }
        }
        __syncthreads();
    }
    float bb[8];
    #pragma unroll
    for (int j = 0; j < 8; j++) bb[j] = bl[tx * 8 + j];
    #pragma unroll
    for (int i = 0; i < 8; i++) {
        int gr = m0 + ty * 8 + i;
        if (gr < N_NODES) {
            float o[8];
            #pragma unroll
            for (int j = 0; j < 4; j++)
                UNPACK2(o[2 * j], o[2 * j + 1], acc2[i][j]);
            float4 o0 = make_float4(o[0] + bb[0], o[1] + bb[1], o[2] + bb[2], o[3] + bb[3]);
            float4 o1 = make_float4(o[4] + bb[4], o[5] + bb[5], o[6] + bb[6], o[7] + bb[7]);
            *(float4*)(out + gr * 64 + tx * 8)     = o0;
            *(float4*)(out + gr * 64 + tx * 8 + 4) = o1;
        }
    }
}

// ---------------- launch ----------------
extern "C" void kernel_launch(void* const* d_in, const int* in_sizes, int n_in,
                              void* d_out, int out_size) {
    const float* x   = (const float*)d_in[0];
    const int*   y   = (const int*)d_in[1];
    const int*   ei  = (const int*)d_in[2];
    const float* emb = (const float*)d_in[3];
    const float* Wq = (const float*)d_in[4];  const float* bq = (const float*)d_in[5];
    const float* Wk = (const float*)d_in[6];  const float* bk = (const float*)d_in[7];
    const float* Wv = (const float*)d_in[8];  const float* bv = (const float*)d_in[9];
    const float* Ws = (const float*)d_in[10]; const float* bs = (const float*)d_in[11];
    const float* Wl = (const float*)d_in[12]; const float* bl = (const float*)d_in[13];
    float* out = (float*)d_out;

    k_zero   <<<(N_NODES / 4 + 255) / 256, 256>>>();
    k_hist   <<<(E_EDGES + 255) / 256, 256>>>(ei);
    k_xy     <<<(N_NODES * (F / 4) + 255) / 256, 256>>>(x, y, emb);
    k_scan   <<<1, 1024>>>();
    k_scatter<<<(E_EDGES + 255) / 256, 256>>>(ei);
    k_proj   <<<dim3((N_NODES + 127) / 128, 4), 256>>>(Wq, bq, Wk, bk, Wv, bv, Ws, bs);
    k_agg    <<<(N_NODES + 7) / 8, 256>>>();
    k_cls    <<<(N_NODES + 127) / 128, 128>>>(Wl, bl, out);
}

// round 7
// speedup vs baseline: 1.2773x; 1.2773x over previous
#include <cuda_runtime.h>
#include <cuda_bf16.h>
#include <math.h>

#define N_NODES 40000
#define E_EDGES 640000
#define F       128
#define HD      128
#define NHEADS  4
#define VOCABV  64
#define SCAN_BLOCKS ((N_NODES + 255) / 256)   // 157

// packed fp32x2 helpers (sm_100a+)
#define FMA2(d, a, b, c) \
    asm("fma.rn.f32x2 %0, %1, %2, %3;" : "=l"(d) : "l"(a), "l"(b), "l"(c))
#define PACK_DUP(d, f) \
    asm("mov.b64 %0, {%1, %1};" : "=l"(d) : "f"(f))
#define UNPACK2(lo, hi, d) \
    asm("mov.b64 {%0, %1}, %2;" : "=f"(lo), "=f"(hi) : "l"(d))

// ---------------- scratch ----------------
__device__ unsigned g_xh [N_NODES * F / 2];   // bf16 hi pairs of x_y
__device__ unsigned g_xl [N_NODES * F / 2];   // bf16 lo pairs
__device__ float g_q   [N_NODES * HD];
__device__ float g_k   [N_NODES * HD];
__device__ float g_v   [N_NODES * HD];
__device__ float g_skip[N_NODES * HD];
__device__ float g_feat[N_NODES * HD];        // final per-node feature
__device__ int   g_cnt [N_NODES];             // per-dst degree
__device__ int   g_start[N_NODES + 1];        // CSR offsets
__device__ int   g_cur [N_NODES];             // scatter cursors
__device__ int   g_sorted[E_EDGES];           // src ids grouped by dst
__device__ int   g_bsum[SCAN_BLOCKS];         // per-block sums for scan

__device__ __forceinline__ unsigned pack_bf16(float lo, float hi) {
    unsigned r;
    asm("cvt.rn.bf16x2.f32 %0, %1, %2;" : "=r"(r) : "f"(hi), "f"(lo));
    return r;
}

__device__ __forceinline__ void mma_bf16(float* d, const unsigned* a, const unsigned* b) {
    asm("mma.sync.aligned.m16n8k16.row.col.f32.bf16.bf16.f32 "
        "{%0,%1,%2,%3}, {%4,%5,%6,%7}, {%8,%9}, {%0,%1,%2,%3};"
        : "+f"(d[0]), "+f"(d[1]), "+f"(d[2]), "+f"(d[3])
        : "r"(a[0]), "r"(a[1]), "r"(a[2]), "r"(a[3]), "r"(b[0]), "r"(b[1]));
}

// ---------------- K0: x_y = x + emb[y], split to bf16 hi/lo ----------------
__global__ void k_xy(const float* __restrict__ x,
                     const int* __restrict__ y,
                     const float* __restrict__ emb) {
    int i = blockIdx.x * blockDim.x + threadIdx.x;
    if (i >= N_NODES * (F / 4)) return;
    int n  = i >> 5;
    int f4 = i & 31;
    int yv = y[n];
    float4 xv = ((const float4*)x)[i];
    float4 ev = *((const float4*)(emb + yv * F) + f4);
    float r[4] = { xv.x + ev.x, xv.y + ev.y, xv.z + ev.z, xv.w + ev.w };
    unsigned h[2], l[2];
    #pragma unroll
    for (int p = 0; p < 2; p++) {
        float a = r[2 * p], b = r[2 * p + 1];
        float ha = __bfloat162float(__float2bfloat16_rn(a));
        float hb = __bfloat162float(__float2bfloat16_rn(b));
        h[p] = pack_bf16(ha, hb);
        l[p] = pack_bf16(a - ha, b - hb);
    }
    ((uint2*)g_xh)[i] = make_uint2(h[0], h[1]);
    ((uint2*)g_xl)[i] = make_uint2(l[0], l[1]);
}

// ---------------- zero degree counters ----------------
__global__ void k_zero() {
    int i = blockIdx.x * blockDim.x + threadIdx.x;
    if (i < N_NODES / 4) ((int4*)g_cnt)[i] = make_int4(0, 0, 0, 0);
}

// ---------------- CSR pass 1: histogram of dst ----------------
__global__ void k_hist(const int* __restrict__ ei) {
    int i = blockIdx.x * blockDim.x + threadIdx.x;
    if (i < E_EDGES) atomicAdd(&g_cnt[ei[E_EDGES + i]], 1);
}

// ---------------- CSR scan A: per-block inclusive scan + block sums ----------
__global__ void __launch_bounds__(256)
k_scan_local() {
    __shared__ int ps[256];
    int tid = threadIdx.x;
    int i   = blockIdx.x * 256 + tid;
    int v = (i < N_NODES) ? g_cnt[i] : 0;
    ps[tid] = v;
    __syncthreads();
    #pragma unroll
    for (int d = 1; d < 256; d <<= 1) {
        int t = (tid >= d) ? ps[tid - d] : 0;
        __syncthreads();
        ps[tid] += t;
        __syncthreads();
    }
    if (i < N_NODES) g_start[i] = ps[tid];     // inclusive local
    if (tid == 255) g_bsum[blockIdx.x] = ps[255];
}

// ---------------- CSR scan B: exclusive scan of block sums (1 block) ---------
__global__ void __launch_bounds__(256)
k_scan_bsum() {
    __shared__ int ps[256];
    int tid = threadIdx.x;
    int v = (tid < SCAN_BLOCKS) ? g_bsum[tid] : 0;
    ps[tid] = v;
    __syncthreads();
    #pragma unroll
    for (int d = 1; d < 256; d <<= 1) {
        int t = (tid >= d) ? ps[tid - d] : 0;
        __syncthreads();
        ps[tid] += t;
        __syncthreads();
    }
    if (tid < SCAN_BLOCKS) g_bsum[tid] = ps[tid] - v;   // exclusive
}

// ---------------- CSR scan C: apply offsets, write exclusive g_start/g_cur ---
__global__ void __launch_bounds__(256)
k_scan_apply() {
    int i = blockIdx.x * 256 + threadIdx.x;
    if (i >= N_NODES) return;
    int ex = g_start[i] - g_cnt[i] + g_bsum[blockIdx.x];
    g_start[i] = ex;
    g_cur[i]   = ex;
    if (i == 0) g_start[N_NODES] = E_EDGES;
}

// ---------------- CSR pass 3: scatter src grouped by dst ----------------
__global__ void k_scatter(const int* __restrict__ ei) {
    int i = blockIdx.x * blockDim.x + threadIdx.x;
    if (i >= E_EDGES) return;
    int src = ei[i];
    int dst = ei[E_EDGES + i];
    int pos = atomicAdd(&g_cur[dst], 1);
    g_sorted[pos] = src;
}

// ---------------- K1: tensor-core projection GEMM (bf16 3-term split) --------
__global__ void __launch_bounds__(256, 2)
k_proj(const float* __restrict__ Wq, const float* __restrict__ bq,
       const float* __restrict__ Wk, const float* __restrict__ bk,
       const float* __restrict__ Wv, const float* __restrict__ bv,
       const float* __restrict__ Ws, const float* __restrict__ bs) {
    const float* W; const float* bias; float* out;
    switch (blockIdx.y) {
        case 0:  W = Wq; bias = bq; out = g_q;    break;
        case 1:  W = Wk; bias = bk; out = g_k;    break;
        case 2:  W = Wv; bias = bv; out = g_v;    break;
        default: W = Ws; bias = bs; out = g_skip; break;
    }
    __shared__ unsigned Ah[128 * 9], Al[128 * 9], Bh[128 * 9], Bl[128 * 9];

    int tid  = threadIdx.x;
    int wid  = tid >> 5, lane = tid & 31;
    int wm   = wid >> 1;
    int wn   = wid & 1;
    int g    = lane >> 2;
    int tig  = lane & 3;
    int m0   = blockIdx.x * 128;

    float C[2][8][4];
    #pragma unroll
    for (int mt = 0; mt < 2; mt++)
        #pragma unroll
        for (int nt = 0; nt < 8; nt++)
            #pragma unroll
            for (int c = 0; c < 4; c++) C[mt][nt][c] = 0.f;

    for (int kc = 0; kc < 128; kc += 16) {
        #pragma unroll
        for (int t = 0; t < 4; t++) {
            int idx = tid + t * 256;
            int row = idx >> 3, kp = idx & 7;
            int gr  = m0 + row;
            unsigned vh = 0u, vl = 0u;
            if (gr < N_NODES) {
                int src = gr * 64 + (kc >> 1) + kp;
                vh = g_xh[src];
                vl = g_xl[src];
            }
            Ah[row * 9 + kp] = vh;
            Al[row * 9 + kp] = vl;
        }
        #pragma unroll
        for (int t = 0; t < 4; t++) {
            int idx = tid + t * 256;
            int n  = idx & 127, kp = idx >> 7;
            float w0 = W[(kc + 2 * kp)     * 128 + n];
            float w1 = W[(kc + 2 * kp + 1) * 128 + n];
            float h0 = __bfloat162float(__float2bfloat16_rn(w0));
            float h1 = __bfloat162float(__float2bfloat16_rn(w1));
            Bh[n * 9 + kp] = pack_bf16(h0, h1);
            Bl[n * 9 + kp] = pack_bf16(w0 - h0, w1 - h1);
        }
        __syncthreads();

        unsigned ah[2][4], al[2][4];
        #pragma unroll
        for (int mt = 0; mt < 2; mt++) {
            int base = wm * 32 + mt * 16;
            ah[mt][0] = Ah[(base + g)     * 9 + tig];
            ah[mt][1] = Ah[(base + g + 8) * 9 + tig];
            ah[mt][2] = Ah[(base + g)     * 9 + tig + 4];
            ah[mt][3] = Ah[(base + g + 8) * 9 + tig + 4];
            al[mt][0] = Al[(base + g)     * 9 + tig];
            al[mt][1] = Al[(base + g + 8) * 9 + tig];
            al[mt][2] = Al[(base + g)     * 9 + tig + 4];
            al[mt][3] = Al[(base + g + 8) * 9 + tig + 4];
        }
        #pragma unroll
        for (int nt = 0; nt < 8; nt++) {
            int nb = wn * 64 + nt * 8;
            unsigned bh[2] = { Bh[(nb + g) * 9 + tig], Bh[(nb + g) * 9 + tig + 4] };
            unsigned bl[2] = { Bl[(nb + g) * 9 + tig], Bl[(nb + g) * 9 + tig + 4] };
            #pragma unroll
            for (int mt = 0; mt < 2; mt++) {
                mma_bf16(C[mt][nt], ah[mt], bh);
                mma_bf16(C[mt][nt], ah[mt], bl);
                mma_bf16(C[mt][nt], al[mt], bh);
            }
        }
        __syncthreads();
    }

    #pragma unroll
    for (int nt = 0; nt < 8; nt++) {
        int col = wn * 64 + nt * 8 + 2 * tig;
        float2 b2 = *(const float2*)(bias + col);
        #pragma unroll
        for (int mt = 0; mt < 2; mt++) {
            int r0 = m0 + wm * 32 + mt * 16 + g;
            int r1 = r0 + 8;
            if (r0 < N_NODES)
                *(float2*)(out + r0 * 128 + col) =
                    make_float2(C[mt][nt][0] + b2.x, C[mt][nt][1] + b2.y);
            if (r1 < N_NODES)
                *(float2*)(out + r1 * 128 + col) =
                    make_float2(C[mt][nt][2] + b2.x, C[mt][nt][3] + b2.y);
        }
    }
}

// ---------------- K2: CSR aggregation, warp per dst node ----------------
__global__ void __launch_bounds__(256)
k_agg(void) {
    int n    = blockIdx.x * 8 + (threadIdx.x >> 5);
    int lane = threadIdx.x & 31;
    if (n >= N_NODES) return;
    int s0 = g_start[n];
    int s1 = g_start[n + 1];

    float4 qv = *(const float4*)(g_q + n * 128 + lane * 4);
    float4 acc = make_float4(0.f, 0.f, 0.f, 0.f);
    float den = 0.f;

    int e = s0;
    float4 kn, vn;
    if (e < s1) {
        int s = g_sorted[e];
        kn = *(const float4*)(g_k + s * 128 + lane * 4);
        vn = *(const float4*)(g_v + s * 128 + lane * 4);
    }
    while (e < s1) {
        float4 kc = kn, vc = vn;
        int en = e + 1;
        if (en < s1) {
            int s = g_sorted[en];
            kn = *(const float4*)(g_k + s * 128 + lane * 4);
            vn = *(const float4*)(g_v + s * 128 + lane * 4);
        }
        float sdot = qv.x * kc.x + qv.y * kc.y + qv.z * kc.z + qv.w * kc.w;
        sdot += __shfl_xor_sync(0xffffffffu, sdot, 1);
        sdot += __shfl_xor_sync(0xffffffffu, sdot, 2);
        sdot += __shfl_xor_sync(0xffffffffu, sdot, 4);
        float ea = __expf(sdot * 0.17677669529663687f);   // 1/sqrt(32)
        den += ea;
        acc.x = fmaf(ea, vc.x, acc.x);
        acc.y = fmaf(ea, vc.y, acc.y);
        acc.z = fmaf(ea, vc.z, acc.z);
        acc.w = fmaf(ea, vc.w, acc.w);
        e = en;
    }
    float inv = (den > 0.f) ? (1.0f / den) : 0.f;
    float4 sk = *(const float4*)(g_skip + n * 128 + lane * 4);
    float4 ft = make_float4(fmaf(acc.x, inv, sk.x), fmaf(acc.y, inv, sk.y),
                            fmaf(acc.z, inv, sk.z), fmaf(acc.w, inv, sk.w));
    *(float4*)(g_feat + n * 128 + lane * 4) = ft;
}

// ---------------- K3: classifier out = g_feat @ Wl + bl, f32x2 ----------------
__global__ void __launch_bounds__(128, 4)
k_cls(const float* __restrict__ Wl, const float* __restrict__ bl,
      float* __restrict__ out) {
    __shared__ float As[16][132];
    __shared__ float Bs[16][68];
    int tid = threadIdx.x;
    int m0  = blockIdx.x * 128;
    int ty  = tid >> 3;
    int tx  = tid & 7;

    unsigned long long acc2[8][4];
    #pragma unroll
    for (int i = 0; i < 8; i++)
        #pragma unroll
        for (int j = 0; j < 4; j++) acc2[i][j] = 0ULL;

    for (int kc = 0; kc < 128; kc += 16) {
        #pragma unroll
        for (int it = 0; it < 4; it++) {
            int j   = tid + it * 128;
            int row = j >> 2;
            int k4  = j & 3;
            int gr  = m0 + row;
            float4 av = make_float4(0.f, 0.f, 0.f, 0.f);
            if (gr < N_NODES)
                av = *(const float4*)(g_feat + gr * 128 + kc + k4 * 4);
            As[k4 * 4 + 0][row] = av.x;
            As[k4 * 4 + 1][row] = av.y;
            As[k4 * 4 + 2][row] = av.z;
            As[k4 * 4 + 3][row] = av.w;
        }
        #pragma unroll
        for (int it = 0; it < 2; it++) {
            int j  = tid + it * 128;
            int kk = j >> 4;
            int n4 = j & 15;
            float4 wv = *(const float4*)(Wl + (kc + kk) * 64 + n4 * 4);
            *(float4*)(&Bs[kk][n4 * 4]) = wv;
        }
        __syncthreads();
        #pragma unroll
        for (int k = 0; k < 16; k++) {
            float a[8];
            *(float4*)(a)     = *(const float4*)(&As[k][ty * 8]);
            *(float4*)(a + 4) = *(const float4*)(&As[k][ty * 8 + 4]);
            unsigned long long b2[4];
            #pragma unroll
            for (int j = 0; j < 4; j++)
                b2[j] = *(const unsigned long long*)(&Bs[k][tx * 8 + j * 2]);
            #pragma unroll
            for (int i = 0; i < 8; i++) {
                unsigned long long av;
                PACK_DUP(av, a[i]);
                #pragma unroll
                for (int j = 0; j < 4; j++)
                    FMA2(acc2[i][j], av, b2[j], acc2[i][j]);
            }
        }
        __syncthreads();
    }
    float bb[8];
    #pragma unroll
    for (int j = 0; j < 8; j++) bb[j] = bl[tx * 8 + j];
    #pragma unroll
    for (int i = 0; i < 8; i++) {
        int gr = m0 + ty * 8 + i;
        if (gr < N_NODES) {
            float o[8];
            #pragma unroll
            for (int j = 0; j < 4; j++)
                UNPACK2(o[2 * j], o[2 * j + 1], acc2[i][j]);
            float4 o0 = make_float4(o[0] + bb[0], o[1] + bb[1], o[2] + bb[2], o[3] + bb[3]);
            float4 o1 = make_float4(o[4] + bb[4], o[5] + bb[5], o[6] + bb[6], o[7] + bb[7]);
            *(float4*)(out + gr * 64 + tx * 8)     = o0;
            *(float4*)(out + gr * 64 + tx * 8 + 4) = o1;
        }
    }
}

// ---------------- launch ----------------
extern "C" void kernel_launch(void* const* d_in, const int* in_sizes, int n_in,
                              void* d_out, int out_size) {
    const float* x   = (const float*)d_in[0];
    const int*   y   = (const int*)d_in[1];
    const int*   ei  = (const int*)d_in[2];
    const float* emb = (const float*)d_in[3];
    const float* Wq = (const float*)d_in[4];  const float* bq = (const float*)d_in[5];
    const float* Wk = (const float*)d_in[6];  const float* bk = (const float*)d_in[7];
    const float* Wv = (const float*)d_in[8];  const float* bv = (const float*)d_in[9];
    const float* Ws = (const float*)d_in[10]; const float* bs = (const float*)d_in[11];
    const float* Wl = (const float*)d_in[12]; const float* bl = (const float*)d_in[13];
    float* out = (float*)d_out;

    k_zero      <<<(N_NODES / 4 + 255) / 256, 256>>>();
    k_hist      <<<(E_EDGES + 255) / 256, 256>>>(ei);
    k_xy        <<<(N_NODES * (F / 4) + 255) / 256, 256>>>(x, y, emb);
    k_scan_local<<<SCAN_BLOCKS, 256>>>();
    k_scan_bsum <<<1, 256>>>();
    k_scan_apply<<<SCAN_BLOCKS, 256>>>();
    k_scatter   <<<(E_EDGES + 255) / 256, 256>>>(ei);
    k_proj      <<<dim3((N_NODES + 127) / 128, 4), 256>>>(Wq, bq, Wk, bk, Wv, bv, Ws, bs);
    k_agg       <<<(N_NODES + 7) / 8, 256>>>();
    k_cls       <<<(N_NODES + 127) / 128, 128>>>(Wl, bl, out);
}

// round 8
// speedup vs baseline: 1.3016x; 1.0191x over previous
#include <cuda_runtime.h>
#include <cuda_bf16.h>
#include <math.h>

#define N_NODES 40000
#define E_EDGES 640000
#define F       128
#define HD      128
#define NHEADS  4
#define VOCABV  64
#define SCAN_BLOCKS ((N_NODES + 255) / 256)   // 157

// packed fp32x2 helpers (sm_100a+)
#define FMA2(d, a, b, c) \
    asm("fma.rn.f32x2 %0, %1, %2, %3;" : "=l"(d) : "l"(a), "l"(b), "l"(c))
#define PACK_DUP(d, f) \
    asm("mov.b64 %0, {%1, %1};" : "=l"(d) : "f"(f))
#define UNPACK2(lo, hi, d) \
    asm("mov.b64 {%0, %1}, %2;" : "=f"(lo), "=f"(hi) : "l"(d))

// A smem row stride (words) for full-K residency
#define ASTR 66
// proj dynamic smem: Ah + Al + 2*Bh + 2*Bl
#define PROJ_SMEM_BYTES ((128 * ASTR * 2 + 2 * 1152 * 2) * 4)

// ---------------- scratch ----------------
__device__ unsigned g_xh [N_NODES * F / 2];   // bf16 hi pairs of x_y (k-pairs)
__device__ unsigned g_xl [N_NODES * F / 2];
__device__ unsigned g_Wh [4 * 64 * 128];      // W bf16 hi, k-major: [w][kp*128+n]
__device__ unsigned g_Wl [4 * 64 * 128];
__device__ float g_q   [N_NODES * HD];
__device__ float g_k   [N_NODES * HD];
__device__ float g_v   [N_NODES * HD];
__device__ float g_skip[N_NODES * HD];
__device__ float g_feat[N_NODES * HD];
__device__ int   g_cnt [N_NODES];
__device__ int   g_start[N_NODES + 1];
__device__ int   g_cur [N_NODES];
__device__ int   g_sorted[E_EDGES];
__device__ int   g_bsum[SCAN_BLOCKS];

__device__ __forceinline__ unsigned pack_bf16(float lo, float hi) {
    unsigned r;
    asm("cvt.rn.bf16x2.f32 %0, %1, %2;" : "=r"(r) : "f"(hi), "f"(lo));
    return r;
}

__device__ __forceinline__ void mma_bf16(float* d, const unsigned* a, const unsigned* b) {
    asm("mma.sync.aligned.m16n8k16.row.col.f32.bf16.bf16.f32 "
        "{%0,%1,%2,%3}, {%4,%5,%6,%7}, {%8,%9}, {%0,%1,%2,%3};"
        : "+f"(d[0]), "+f"(d[1]), "+f"(d[2]), "+f"(d[3])
        : "r"(a[0]), "r"(a[1]), "r"(a[2]), "r"(a[3]), "r"(b[0]), "r"(b[1]));
}

// ---------------- K0: x_y = x + emb[y], split to bf16 hi/lo ----------------
__global__ void k_xy(const float* __restrict__ x,
                     const int* __restrict__ y,
                     const float* __restrict__ emb) {
    int i = blockIdx.x * blockDim.x + threadIdx.x;
    if (i >= N_NODES * (F / 4)) return;
    int n  = i >> 5;
    int f4 = i & 31;
    int yv = y[n];
    float4 xv = ((const float4*)x)[i];
    float4 ev = *((const float4*)(emb + yv * F) + f4);
    float r[4] = { xv.x + ev.x, xv.y + ev.y, xv.z + ev.z, xv.w + ev.w };
    unsigned h[2], l[2];
    #pragma unroll
    for (int p = 0; p < 2; p++) {
        float a = r[2 * p], b = r[2 * p + 1];
        float ha = __bfloat162float(__float2bfloat16_rn(a));
        float hb = __bfloat162float(__float2bfloat16_rn(b));
        h[p] = pack_bf16(ha, hb);
        l[p] = pack_bf16(a - ha, b - hb);
    }
    ((uint2*)g_xh)[i] = make_uint2(h[0], h[1]);
    ((uint2*)g_xl)[i] = make_uint2(l[0], l[1]);
}

// ---------------- split all 4 W matrices to bf16 hi/lo (k-major packed) ------
__global__ void k_wsplit(const float* __restrict__ Wq, const float* __restrict__ Wk,
                         const float* __restrict__ Wv, const float* __restrict__ Ws) {
    int i = blockIdx.x * blockDim.x + threadIdx.x;   // 4*64*128
    if (i >= 4 * 64 * 128) return;
    int w   = i >> 13;
    int rem = i & 8191;
    int kp  = rem >> 7;
    int n   = rem & 127;
    const float* W = (w == 0) ? Wq : (w == 1) ? Wk : (w == 2) ? Wv : Ws;
    float w0 = W[(2 * kp)     * 128 + n];
    float w1 = W[(2 * kp + 1) * 128 + n];
    float h0 = __bfloat162float(__float2bfloat16_rn(w0));
    float h1 = __bfloat162float(__float2bfloat16_rn(w1));
    g_Wh[i] = pack_bf16(h0, h1);
    g_Wl[i] = pack_bf16(w0 - h0, w1 - h1);
}

// ---------------- zero degree counters ----------------
__global__ void k_zero() {
    int i = blockIdx.x * blockDim.x + threadIdx.x;
    if (i < N_NODES / 4) ((int4*)g_cnt)[i] = make_int4(0, 0, 0, 0);
}

// ---------------- CSR pass 1: histogram of dst ----------------
__global__ void k_hist(const int* __restrict__ ei) {
    int i = blockIdx.x * blockDim.x + threadIdx.x;
    if (i < E_EDGES) atomicAdd(&g_cnt[ei[E_EDGES + i]], 1);
}

// ---------------- CSR scan A: per-block inclusive scan + block sums ----------
__global__ void __launch_bounds__(256)
k_scan_local() {
    __shared__ int ps[256];
    int tid = threadIdx.x;
    int i   = blockIdx.x * 256 + tid;
    int v = (i < N_NODES) ? g_cnt[i] : 0;
    ps[tid] = v;
    __syncthreads();
    #pragma unroll
    for (int d = 1; d < 256; d <<= 1) {
        int t = (tid >= d) ? ps[tid - d] : 0;
        __syncthreads();
        ps[tid] += t;
        __syncthreads();
    }
    if (i < N_NODES) g_start[i] = ps[tid];
    if (tid == 255) g_bsum[blockIdx.x] = ps[255];
}

// ---------------- CSR scan B: exclusive scan of block sums ----------
__global__ void __launch_bounds__(256)
k_scan_bsum() {
    __shared__ int ps[256];
    int tid = threadIdx.x;
    int v = (tid < SCAN_BLOCKS) ? g_bsum[tid] : 0;
    ps[tid] = v;
    __syncthreads();
    #pragma unroll
    for (int d = 1; d < 256; d <<= 1) {
        int t = (tid >= d) ? ps[tid - d] : 0;
        __syncthreads();
        ps[tid] += t;
        __syncthreads();
    }
    if (tid < SCAN_BLOCKS) g_bsum[tid] = ps[tid] - v;
}

// ---------------- CSR scan C: apply offsets ----------
__global__ void __launch_bounds__(256)
k_scan_apply() {
    int i = blockIdx.x * 256 + threadIdx.x;
    if (i >= N_NODES) return;
    int ex = g_start[i] - g_cnt[i] + g_bsum[blockIdx.x];
    g_start[i] = ex;
    g_cur[i]   = ex;
    if (i == 0) g_start[N_NODES] = E_EDGES;
}

// ---------------- CSR pass 3: scatter src grouped by dst ----------------
__global__ void k_scatter(const int* __restrict__ ei) {
    int i = blockIdx.x * blockDim.x + threadIdx.x;
    if (i >= E_EDGES) return;
    int src = ei[i];
    int dst = ei[E_EDGES + i];
    int pos = atomicAdd(&g_cur[dst], 1);
    g_sorted[pos] = src;
}

// ---------------- K1: projection GEMM, A resident full-K, B double-buffered --
// grid 313 blocks x 256 threads (8 warps = 4m x 2n); loops y=0..3 inside.
__global__ void __launch_bounds__(256, 2)
k_proj(const float* __restrict__ bq, const float* __restrict__ bk,
       const float* __restrict__ bv, const float* __restrict__ bs) {
    extern __shared__ unsigned smem[];
    unsigned* Ah = smem;                     // 128*ASTR
    unsigned* Al = Ah + 128 * ASTR;
    unsigned* Bh = Al + 128 * ASTR;          // 2 bufs x 128*9
    unsigned* Bl = Bh + 2 * 1152;

    int tid  = threadIdx.x;
    int wid  = tid >> 5, lane = tid & 31;
    int wm   = wid >> 1;
    int wn   = wid & 1;
    int g    = lane >> 2;
    int tig  = lane & 3;
    int m0   = blockIdx.x * 128;

    // stage full-K A tile once (8192 entries per array)
    #pragma unroll
    for (int t = 0; t < 32; t++) {
        int idx = tid + t * 256;
        int row = idx >> 6, kp = idx & 63;
        int gr  = m0 + row;
        unsigned vh = 0u, vl = 0u;
        if (gr < N_NODES) {
            int src = gr * 64 + kp;
            vh = g_xh[src];
            vl = g_xl[src];
        }
        Ah[row * ASTR + kp] = vh;
        Al[row * ASTR + kp] = vl;
    }

    for (int y = 0; y < 4; y++) {
        const unsigned* Wh = g_Wh + y * 8192;
        const unsigned* Wl = g_Wl + y * 8192;
        const float* bias = (y == 0) ? bq : (y == 1) ? bk : (y == 2) ? bv : bs;
        float* out = (y == 0) ? g_q : (y == 1) ? g_k : (y == 2) ? g_v : g_skip;

        float C[2][8][4];
        #pragma unroll
        for (int mt = 0; mt < 2; mt++)
            #pragma unroll
            for (int nt = 0; nt < 8; nt++)
                #pragma unroll
                for (int c = 0; c < 4; c++) C[mt][nt][c] = 0.f;

        // stage B chunk 0 into buf 0
        #pragma unroll
        for (int t = 0; t < 4; t++) {
            int idx = tid + t * 256;
            int n = idx & 127, kp = idx >> 7;
            Bh[n * 9 + kp] = Wh[kp * 128 + n];
            Bl[n * 9 + kp] = Wl[kp * 128 + n];
        }
        __syncthreads();   // also covers A staging on y==0

        for (int ck = 0; ck < 8; ck++) {
            int buf = ck & 1;
            if (ck < 7) {
                int nbuf = buf ^ 1;
                #pragma unroll
                for (int t = 0; t < 4; t++) {
                    int idx = tid + t * 256;
                    int n = idx & 127, kp = idx >> 7;
                    Bh[nbuf * 1152 + n * 9 + kp] = Wh[((ck + 1) * 8 + kp) * 128 + n];
                    Bl[nbuf * 1152 + n * 9 + kp] = Wl[((ck + 1) * 8 + kp) * 128 + n];
                }
            }
            int ck8 = ck * 8;
            unsigned ah[2][4], al[2][4];
            #pragma unroll
            for (int mt = 0; mt < 2; mt++) {
                int base = wm * 32 + mt * 16;
                ah[mt][0] = Ah[(base + g)     * ASTR + ck8 + tig];
                ah[mt][1] = Ah[(base + g + 8) * ASTR + ck8 + tig];
                ah[mt][2] = Ah[(base + g)     * ASTR + ck8 + tig + 4];
                ah[mt][3] = Ah[(base + g + 8) * ASTR + ck8 + tig + 4];
                al[mt][0] = Al[(base + g)     * ASTR + ck8 + tig];
                al[mt][1] = Al[(base + g + 8) * ASTR + ck8 + tig];
                al[mt][2] = Al[(base + g)     * ASTR + ck8 + tig + 4];
                al[mt][3] = Al[(base + g + 8) * ASTR + ck8 + tig + 4];
            }
            #pragma unroll
            for (int nt = 0; nt < 8; nt++) {
                int nb = wn * 64 + nt * 8;
                unsigned bh[2] = { Bh[buf * 1152 + (nb + g) * 9 + tig],
                                   Bh[buf * 1152 + (nb + g) * 9 + tig + 4] };
                unsigned bl[2] = { Bl[buf * 1152 + (nb + g) * 9 + tig],
                                   Bl[buf * 1152 + (nb + g) * 9 + tig + 4] };
                #pragma unroll
                for (int mt = 0; mt < 2; mt++) {
                    mma_bf16(C[mt][nt], ah[mt], bh);
                    mma_bf16(C[mt][nt], ah[mt], bl);
                    mma_bf16(C[mt][nt], al[mt], bh);
                }
            }
            __syncthreads();
        }

        // epilogue
        #pragma unroll
        for (int nt = 0; nt < 8; nt++) {
            int col = wn * 64 + nt * 8 + 2 * tig;
            float2 b2 = *(const float2*)(bias + col);
            #pragma unroll
            for (int mt = 0; mt < 2; mt++) {
                int r0 = m0 + wm * 32 + mt * 16 + g;
                int r1 = r0 + 8;
                if (r0 < N_NODES)
                    *(float2*)(out + r0 * 128 + col) =
                        make_float2(C[mt][nt][0] + b2.x, C[mt][nt][1] + b2.y);
                if (r1 < N_NODES)
                    *(float2*)(out + r1 * 128 + col) =
                        make_float2(C[mt][nt][2] + b2.x, C[mt][nt][3] + b2.y);
            }
        }
    }
}

// ---------------- K2: CSR aggregation, warp per dst node, pairwise+prefetch --
__global__ void __launch_bounds__(256)
k_agg(void) {
    int n    = blockIdx.x * 8 + (threadIdx.x >> 5);
    int lane = threadIdx.x & 31;
    if (n >= N_NODES) return;
    int s0 = g_start[n];
    int s1 = g_start[n + 1];

    float4 qv = *(const float4*)(g_q + n * 128 + lane * 4);
    float4 acc = make_float4(0.f, 0.f, 0.f, 0.f);
    float den = 0.f;

    #define AGG_STEP(kc, vc) do {                                              \
        float sd = qv.x * (kc).x + qv.y * (kc).y + qv.z * (kc).z + qv.w * (kc).w; \
        sd += __shfl_xor_sync(0xffffffffu, sd, 1);                             \
        sd += __shfl_xor_sync(0xffffffffu, sd, 2);                             \
        sd += __shfl_xor_sync(0xffffffffu, sd, 4);                             \
        float ea = __expf(sd * 0.17677669529663687f);                          \
        den += ea;                                                             \
        acc.x = fmaf(ea, (vc).x, acc.x);                                       \
        acc.y = fmaf(ea, (vc).y, acc.y);                                       \
        acc.z = fmaf(ea, (vc).z, acc.z);                                       \
        acc.w = fmaf(ea, (vc).w, acc.w);                                       \
    } while (0)

    int e = s0;
    if (s1 - s0 >= 2) {
        int sA = g_sorted[e], sB = g_sorted[e + 1];
        float4 kA = *(const float4*)(g_k + sA * 128 + lane * 4);
        float4 vA = *(const float4*)(g_v + sA * 128 + lane * 4);
        float4 kB = *(const float4*)(g_k + sB * 128 + lane * 4);
        float4 vB = *(const float4*)(g_v + sB * 128 + lane * 4);
        e += 2;
        while (e + 1 < s1) {
            int sC = g_sorted[e], sD = g_sorted[e + 1];
            float4 kC = *(const float4*)(g_k + sC * 128 + lane * 4);
            float4 vC = *(const float4*)(g_v + sC * 128 + lane * 4);
            float4 kD = *(const float4*)(g_k + sD * 128 + lane * 4);
            float4 vD = *(const float4*)(g_v + sD * 128 + lane * 4);
            AGG_STEP(kA, vA);
            AGG_STEP(kB, vB);
            kA = kC; vA = vC; kB = kD; vB = vD;
            e += 2;
        }
        AGG_STEP(kA, vA);
        AGG_STEP(kB, vB);
    }
    if (e < s1) {
        int s = g_sorted[e];
        float4 kc = *(const float4*)(g_k + s * 128 + lane * 4);
        float4 vc = *(const float4*)(g_v + s * 128 + lane * 4);
        AGG_STEP(kc, vc);
    }

    float inv = (den > 0.f) ? (1.0f / den) : 0.f;
    float4 sk = *(const float4*)(g_skip + n * 128 + lane * 4);
    float4 ft = make_float4(fmaf(acc.x, inv, sk.x), fmaf(acc.y, inv, sk.y),
                            fmaf(acc.z, inv, sk.z), fmaf(acc.w, inv, sk.w));
    *(float4*)(g_feat + n * 128 + lane * 4) = ft;
}

// ---------------- K3: classifier out = g_feat @ Wl + bl, f32x2 ----------------
__global__ void __launch_bounds__(128, 4)
k_cls(const float* __restrict__ Wl, const float* __restrict__ bl,
      float* __restrict__ out) {
    __shared__ float As[16][132];
    __shared__ float Bs[16][68];
    int tid = threadIdx.x;
    int m0  = blockIdx.x * 128;
    int ty  = tid >> 3;
    int tx  = tid & 7;

    unsigned long long acc2[8][4];
    #pragma unroll
    for (int i = 0; i < 8; i++)
        #pragma unroll
        for (int j = 0; j < 4; j++) acc2[i][j] = 0ULL;

    for (int kc = 0; kc < 128; kc += 16) {
        #pragma unroll
        for (int it = 0; it < 4; it++) {
            int j   = tid + it * 128;
            int row = j >> 2;
            int k4  = j & 3;
            int gr  = m0 + row;
            float4 av = make_float4(0.f, 0.f, 0.f, 0.f);
            if (gr < N_NODES)
                av = *(const float4*)(g_feat + gr * 128 + kc + k4 * 4);
            As[k4 * 4 + 0][row] = av.x;
            As[k4 * 4 + 1][row] = av.y;
            As[k4 * 4 + 2][row] = av.z;
            As[k4 * 4 + 3][row] = av.w;
        }
        #pragma unroll
        for (int it = 0; it < 2; it++) {
            int j  = tid + it * 128;
            int kk = j >> 4;
            int n4 = j & 15;
            float4 wv = *(const float4*)(Wl + (kc + kk) * 64 + n4 * 4);
            *(float4*)(&Bs[kk][n4 * 4]) = wv;
        }
        __syncthreads();
        #pragma unroll
        for (int k = 0; k < 16; k++) {
            float a[8];
            *(float4*)(a)     = *(const float4*)(&As[k][ty * 8]);
            *(float4*)(a + 4) = *(const float4*)(&As[k][ty * 8 + 4]);
            unsigned long long b2[4];
            #pragma unroll
            for (int j = 0; j < 4; j++)
                b2[j] = *(const unsigned long long*)(&Bs[k][tx * 8 + j * 2]);
            #pragma unroll
            for (int i = 0; i < 8; i++) {
                unsigned long long av;
                PACK_DUP(av, a[i]);
                #pragma unroll
                for (int j = 0; j < 4; j++)
                    FMA2(acc2[i][j], av, b2[j], acc2[i][j]);
            }
        }
        __syncthreads();
    }
    float bb[8];
    #pragma unroll
    for (int j = 0; j < 8; j++) bb[j] = bl[tx * 8 + j];
    #pragma unroll
    for (int i = 0; i < 8; i++) {
        int gr = m0 + ty * 8 + i;
        if (gr < N_NODES) {
            float o[8];
            #pragma unroll
            for (int j = 0; j < 4; j++)
                UNPACK2(o[2 * j], o[2 * j + 1], acc2[i][j]);
            float4 o0 = make_float4(o[0] + bb[0], o[1] + bb[1], o[2] + bb[2], o[3] + bb[3]);
            float4 o1 = make_float4(o[4] + bb[4], o[5] + bb[5], o[6] + bb[6], o[7] + bb[7]);
            *(float4*)(out + gr * 64 + tx * 8)     = o0;
            *(float4*)(out + gr * 64 + tx * 8 + 4) = o1;
        }
    }
}

// ---------------- launch ----------------
extern "C" void kernel_launch(void* const* d_in, const int* in_sizes, int n_in,
                              void* d_out, int out_size) {
    const float* x   = (const float*)d_in[0];
    const int*   y   = (const int*)d_in[1];
    const int*   ei  = (const int*)d_in[2];
    const float* emb = (const float*)d_in[3];
    const float* Wq = (const float*)d_in[4];  const float* bq = (const float*)d_in[5];
    const float* Wk = (const float*)d_in[6];  const float* bk = (const float*)d_in[7];
    const float* Wv = (const float*)d_in[8];  const float* bv = (const float*)d_in[9];
    const float* Ws = (const float*)d_in[10]; const float* bs = (const float*)d_in[11];
    const float* Wl = (const float*)d_in[12]; const float* bl = (const float*)d_in[13];
    float* out = (float*)d_out;

    cudaFuncSetAttribute(k_proj, cudaFuncAttributeMaxDynamicSharedMemorySize,
                         PROJ_SMEM_BYTES);

    k_zero      <<<(N_NODES / 4 + 255) / 256, 256>>>();
    k_hist      <<<(E_EDGES + 255) / 256, 256>>>(ei);
    k_wsplit    <<<(4 * 64 * 128 + 255) / 256, 256>>>(Wq, Wk, Wv, Ws);
    k_xy        <<<(N_NODES * (F / 4) + 255) / 256, 256>>>(x, y, emb);
    k_scan_local<<<SCAN_BLOCKS, 256>>>();
    k_scan_bsum <<<1, 256>>>();
    k_scan_apply<<<SCAN_BLOCKS, 256>>>();
    k_scatter   <<<(E_EDGES + 255) / 256, 256>>>(ei);
    k_proj      <<<(N_NODES + 127) / 128, 256, PROJ_SMEM_BYTES>>>(bq, bk, bv, bs);
    k_agg       <<<(N_NODES + 7) / 8, 256>>>();
    k_cls       <<<(N_NODES + 127) / 128, 128>>>(Wl, bl, out);
}

// round 12
// speedup vs baseline: 1.3408x; 1.0301x over previous
#include <cuda_runtime.h>
#include <cuda_fp16.h>
#include <cstdint>
#include <math.h>

#define N_NODES 40000
#define E_EDGES 640000
#define F       128
#define HD      128
#define NHEADS  4
#define VOCABV  64
#define SCAN_BLOCKS ((N_NODES + 255) / 256)   // 157
#define ASTR    66

// packed fp32x2 helpers (sm_100a+)
#define FMA2(d, a, b, c) \
    asm("fma.rn.f32x2 %0, %1, %2, %3;" : "=l"(d) : "l"(a), "l"(b), "l"(c))
#define PACK_DUP(d, f) \
    asm("mov.b64 %0, {%1, %1};" : "=l"(d) : "f"(f))
#define UNPACK2(lo, hi, d) \
    asm("mov.b64 {%0, %1}, %2;" : "=f"(lo), "=f"(hi) : "l"(d))

// ---------------- scratch ----------------
__device__ unsigned g_xh [N_NODES * F / 2];   // fp16 pairs of x_y (k-pairs)
__device__ unsigned g_Wh [4 * 64 * 128];      // W fp16 hi, k-major: [w][kp*128+n]
__device__ unsigned g_Wl [4 * 64 * 128];      // W fp16 lo
__device__ float g_q   [N_NODES * HD];
__device__ float g_k   [N_NODES * HD];
__device__ float g_v   [N_NODES * HD];
__device__ float g_skip[N_NODES * HD];
__device__ float g_feat[N_NODES * HD];
__device__ int   g_cnt [N_NODES];
__device__ int   g_start[N_NODES + 1];
__device__ int   g_cur [N_NODES];
__device__ int   g_sorted[E_EDGES];
__device__ int   g_bsum[SCAN_BLOCKS];

__device__ __forceinline__ unsigned pack_f16(float lo, float hi) {
    unsigned r;
    asm("cvt.rn.f16x2.f32 %0, %1, %2;" : "=r"(r) : "f"(hi), "f"(lo));
    return r;
}

__device__ __forceinline__ void mma_f16(float* d, const unsigned* a, const unsigned* b) {
    asm("mma.sync.aligned.m16n8k16.row.col.f32.f16.f16.f32 "
        "{%0,%1,%2,%3}, {%4,%5,%6,%7}, {%8,%9}, {%0,%1,%2,%3};"
        : "+f"(d[0]), "+f"(d[1]), "+f"(d[2]), "+f"(d[3])
        : "r"(a[0]), "r"(a[1]), "r"(a[2]), "r"(a[3]), "r"(b[0]), "r"(b[1]));
}

// ---------------- K0 fused: x_y split + zero counters + W split ----------------
// block partition: [0,5000) xy, [5000,5040) zero cnt, [5040,5168) wsplit
__global__ void __launch_bounds__(256)
k_init(const float* __restrict__ x, const int* __restrict__ y,
       const float* __restrict__ emb,
       const float* __restrict__ Wq, const float* __restrict__ Wk,
       const float* __restrict__ Wv, const float* __restrict__ Ws) {
    int b = blockIdx.x;
    int tid = threadIdx.x;
    if (b < 5000) {
        int i = b * 256 + tid;                 // float4 index, exactly N*32
        int n  = i >> 5;
        int f4 = i & 31;
        int yv = y[n];
        float4 xv = ((const float4*)x)[i];
        float4 ev = *((const float4*)(emb + yv * F) + f4);
        unsigned h0 = pack_f16(xv.x + ev.x, xv.y + ev.y);
        unsigned h1 = pack_f16(xv.z + ev.z, xv.w + ev.w);
        ((uint2*)g_xh)[i] = make_uint2(h0, h1);
    } else if (b < 5040) {
        int i = (b - 5000) * 256 + tid;
        if (i < N_NODES / 4) ((int4*)g_cnt)[i] = make_int4(0, 0, 0, 0);
    } else {
        int i = (b - 5040) * 256 + tid;        // 4*64*128 = 32768 exactly
        int w   = i >> 13;
        int rem = i & 8191;
        int kp  = rem >> 7;
        int n   = rem & 127;
        const float* W = (w == 0) ? Wq : (w == 1) ? Wk : (w == 2) ? Wv : Ws;
        float w0 = W[(2 * kp)     * 128 + n];
        float w1 = W[(2 * kp + 1) * 128 + n];
        float h0 = __half2float(__float2half_rn(w0));
        float h1 = __half2float(__float2half_rn(w1));
        g_Wh[i] = pack_f16(h0, h1);
        g_Wl[i] = pack_f16(w0 - h0, w1 - h1);
    }
}

// ---------------- CSR pass 1: histogram of dst ----------------
__global__ void k_hist(const int* __restrict__ ei) {
    int i = blockIdx.x * blockDim.x + threadIdx.x;
    if (i < E_EDGES) atomicAdd(&g_cnt[ei[E_EDGES + i]], 1);
}

// ---------------- CSR scans ----------------
__global__ void __launch_bounds__(256)
k_scan_local() {
    __shared__ int ps[256];
    int tid = threadIdx.x;
    int i   = blockIdx.x * 256 + tid;
    int v = (i < N_NODES) ? g_cnt[i] : 0;
    ps[tid] = v;
    __syncthreads();
    #pragma unroll
    for (int d = 1; d < 256; d <<= 1) {
        int t = (tid >= d) ? ps[tid - d] : 0;
        __syncthreads();
        ps[tid] += t;
        __syncthreads();
    }
    if (i < N_NODES) g_start[i] = ps[tid];
    if (tid == 255) g_bsum[blockIdx.x] = ps[255];
}

__global__ void __launch_bounds__(256)
k_scan_bsum() {
    __shared__ int ps[256];
    int tid = threadIdx.x;
    int v = (tid < SCAN_BLOCKS) ? g_bsum[tid] : 0;
    ps[tid] = v;
    __syncthreads();
    #pragma unroll
    for (int d = 1; d < 256; d <<= 1) {
        int t = (tid >= d) ? ps[tid - d] : 0;
        __syncthreads();
        ps[tid] += t;
        __syncthreads();
    }
    if (tid < SCAN_BLOCKS) g_bsum[tid] = ps[tid] - v;
}

__global__ void __launch_bounds__(256)
k_scan_apply() {
    int i = blockIdx.x * 256 + threadIdx.x;
    if (i >= N_NODES) return;
    int ex = g_start[i] - g_cnt[i] + g_bsum[blockIdx.x];
    g_start[i] = ex;
    g_cur[i]   = ex;
    if (i == 0) g_start[N_NODES] = E_EDGES;
}

// ---------------- CSR scatter ----------------
__global__ void k_scatter(const int* __restrict__ ei) {
    int i = blockIdx.x * blockDim.x + threadIdx.x;
    if (i >= E_EDGES) return;
    int src = ei[i];
    int dst = ei[E_EDGES + i];
    int pos = atomicAdd(&g_cur[dst], 1);
    g_sorted[pos] = src;
}

// ---------------- K1: projection GEMM, fp16 2-term, A resident full-K --------
// grid 313 x 256 threads (8 warps = 4m x 2n); loops y=0..3 inside; B chunk
// double-buffered (stage next chunk while computing current).
__global__ void __launch_bounds__(256, 2)
k_proj(const float* __restrict__ bq, const float* __restrict__ bk,
       const float* __restrict__ bv, const float* __restrict__ bs) {
    __shared__ unsigned Ah[128 * ASTR];      // fp16 pairs, full K
    __shared__ unsigned Bh[2][1152], Bl[2][1152];

    int tid  = threadIdx.x;
    int wid  = tid >> 5, lane = tid & 31;
    int wm   = wid >> 1;            // 0..3 : rows wm*32..+32
    int wn   = wid & 1;             // 0..1 : cols wn*64..+64
    int g    = lane >> 2;           // 0..7
    int tig  = lane & 3;            // 0..3
    int m0   = blockIdx.x * 128;

    // stage full-K A tile once: 8192 words
    #pragma unroll
    for (int t = 0; t < 32; t++) {
        int idx = tid + t * 256;
        int row = idx >> 6, kp = idx & 63;
        int gr  = m0 + row;
        Ah[row * ASTR + kp] = (gr < N_NODES) ? g_xh[gr * 64 + kp] : 0u;
    }
    // stage B chunk (y=0, ck=0) into buf 0
    #pragma unroll
    for (int t = 0; t < 4; t++) {
        int idx = tid + t * 256;
        int n = idx & 127, kp = idx >> 7;
        Bh[0][n * 9 + kp] = g_Wh[kp * 128 + n];
        Bl[0][n * 9 + kp] = g_Wl[kp * 128 + n];
    }
    __syncthreads();

    for (int y = 0; y < 4; y++) {
        const float* bias = (y == 0) ? bq : (y == 1) ? bk : (y == 2) ? bv : bs;
        float* out = (y == 0) ? g_q : (y == 1) ? g_k : (y == 2) ? g_v : g_skip;

        float C[2][8][4];
        #pragma unroll
        for (int mt = 0; mt < 2; mt++)
            #pragma unroll
            for (int nt = 0; nt < 8; nt++)
                #pragma unroll
                for (int c = 0; c < 4; c++) C[mt][nt][c] = 0.f;

        for (int ck = 0; ck < 8; ck++) {
            int it  = y * 8 + ck;           // global chunk counter 0..31
            int buf = it & 1;
            if (it < 31) {                   // stage next chunk into other buf
                int nit = it + 1;
                int nbuf = buf ^ 1;
                const unsigned* Wh = g_Wh + (nit >> 3) * 8192 + (nit & 7) * 8 * 128;
                const unsigned* Wl = g_Wl + (nit >> 3) * 8192 + (nit & 7) * 8 * 128;
                #pragma unroll
                for (int t = 0; t < 4; t++) {
                    int idx = tid + t * 256;
                    int n = idx & 127, kp = idx >> 7;
                    Bh[nbuf][n * 9 + kp] = Wh[kp * 128 + n];
                    Bl[nbuf][n * 9 + kp] = Wl[kp * 128 + n];
                }
            }
            int ck8 = ck * 8;
            unsigned ah[2][4];
            #pragma unroll
            for (int mt = 0; mt < 2; mt++) {
                int base = wm * 32 + mt * 16;
                ah[mt][0] = Ah[(base + g)     * ASTR + ck8 + tig];
                ah[mt][1] = Ah[(base + g + 8) * ASTR + ck8 + tig];
                ah[mt][2] = Ah[(base + g)     * ASTR + ck8 + tig + 4];
                ah[mt][3] = Ah[(base + g + 8) * ASTR + ck8 + tig + 4];
            }
            // term 0: hi, term 1: lo
            #pragma unroll
            for (int term = 0; term < 2; term++) {
                const unsigned* B = term ? Bl[buf] : Bh[buf];
                #pragma unroll
                for (int nt = 0; nt < 8; nt++) {
                    int nb = wn * 64 + nt * 8;
                    unsigned b2[2] = { B[(nb + g) * 9 + tig], B[(nb + g) * 9 + tig + 4] };
                    #pragma unroll
                    for (int mt = 0; mt < 2; mt++)
                        mma_f16(C[mt][nt], ah[mt], b2);
                }
            }
            __syncthreads();
        }

        // epilogue: c0=(g,2tig) c1=(g,2tig+1) c2=(g+8,2tig) c3=(g+8,2tig+1)
        #pragma unroll
        for (int nt = 0; nt < 8; nt++) {
            int col = wn * 64 + nt * 8 + 2 * tig;
            float2 b2 = *(const float2*)(bias + col);
            #pragma unroll
            for (int mt = 0; mt < 2; mt++) {
                int r0 = m0 + wm * 32 + mt * 16 + g;
                int r1 = r0 + 8;
                if (r0 < N_NODES)
                    *(float2*)(out + r0 * 128 + col) =
                        make_float2(C[mt][nt][0] + b2.x, C[mt][nt][1] + b2.y);
                if (r1 < N_NODES)
                    *(float2*)(out + r1 * 128 + col) =
                        make_float2(C[mt][nt][2] + b2.x, C[mt][nt][3] + b2.y);
            }
        }
    }
}

// ---------------- K2: CSR aggregation, warp per dst node, pairwise+prefetch --
__global__ void __launch_bounds__(256)
k_agg(void) {
    int n    = blockIdx.x * 8 + (threadIdx.x >> 5);
    int lane = threadIdx.x & 31;
    if (n >= N_NODES) return;
    int s0 = g_start[n];
    int s1 = g_start[n + 1];

    float4 qv = *(const float4*)(g_q + n * 128 + lane * 4);
    float4 acc = make_float4(0.f, 0.f, 0.f, 0.f);
    float den = 0.f;

    #define AGG_STEP(kc, vc) do {                                              \
        float sd = qv.x * (kc).x + qv.y * (kc).y + qv.z * (kc).z + qv.w * (kc).w; \
        sd += __shfl_xor_sync(0xffffffffu, sd, 1);                             \
        sd += __shfl_xor_sync(0xffffffffu, sd, 2);                             \
        sd += __shfl_xor_sync(0xffffffffu, sd, 4);                             \
        float ea = __expf(sd * 0.17677669529663687f);                          \
        den += ea;                                                             \
        acc.x = fmaf(ea, (vc).x, acc.x);                                       \
        acc.y = fmaf(ea, (vc).y, acc.y);                                       \
        acc.z = fmaf(ea, (vc).z, acc.z);                                       \
        acc.w = fmaf(ea, (vc).w, acc.w);                                       \
    } while (0)

    int e = s0;
    if (s1 - s0 >= 2) {
        int sA = g_sorted[e], sB = g_sorted[e + 1];
        float4 kA = *(const float4*)(g_k + sA * 128 + lane * 4);
        float4 vA = *(const float4*)(g_v + sA * 128 + lane * 4);
        float4 kB = *(const float4*)(g_k + sB * 128 + lane * 4);
        float4 vB = *(const float4*)(g_v + sB * 128 + lane * 4);
        e += 2;
        while (e + 1 < s1) {
            int sC = g_sorted[e], sD = g_sorted[e + 1];
            float4 kC = *(const float4*)(g_k + sC * 128 + lane * 4);
            float4 vC = *(const float4*)(g_v + sC * 128 + lane * 4);
            float4 kD = *(const float4*)(g_k + sD * 128 + lane * 4);
            float4 vD = *(const float4*)(g_v + sD * 128 + lane * 4);
            AGG_STEP(kA, vA);
            AGG_STEP(kB, vB);
            kA = kC; vA = vC; kB = kD; vB = vD;
            e += 2;
        }
        AGG_STEP(kA, vA);
        AGG_STEP(kB, vB);
    }
    if (e < s1) {
        int s = g_sorted[e];
        float4 kc = *(const float4*)(g_k + s * 128 + lane * 4);
        float4 vc = *(const float4*)(g_v + s * 128 + lane * 4);
        AGG_STEP(kc, vc);
    }

    float inv = (den > 0.f) ? (1.0f / den) : 0.f;
    float4 sk = *(const float4*)(g_skip + n * 128 + lane * 4);
    float4 ft = make_float4(fmaf(acc.x, inv, sk.x), fmaf(acc.y, inv, sk.y),
                            fmaf(acc.z, inv, sk.z), fmaf(acc.w, inv, sk.w));
    *(float4*)(g_feat + n * 128 + lane * 4) = ft;
}

// ---------------- K3: classifier out = g_feat @ Wl + bl, f32x2 ----------------
__global__ void __launch_bounds__(128, 4)
k_cls(const float* __restrict__ Wl, const float* __restrict__ bl,
      float* __restrict__ out) {
    __shared__ float As[16][132];
    __shared__ float Bs[16][68];
    int tid = threadIdx.x;
    int m0  = blockIdx.x * 128;
    int ty  = tid >> 3;
    int tx  = tid & 7;

    unsigned long long acc2[8][4];
    #pragma unroll
    for (int i = 0; i < 8; i++)
        #pragma unroll
        for (int j = 0; j < 4; j++) acc2[i][j] = 0ULL;

    for (int kc = 0; kc < 128; kc += 16) {
        #pragma unroll
        for (int it = 0; it < 4; it++) {
            int j   = tid + it * 128;
            int row = j >> 2;
            int k4  = j & 3;
            int gr  = m0 + row;
            float4 av = make_float4(0.f, 0.f, 0.f, 0.f);
            if (gr < N_NODES)
                av = *(const float4*)(g_feat + gr * 128 + kc + k4 * 4);
            As[k4 * 4 + 0][row] = av.x;
            As[k4 * 4 + 1][row] = av.y;
            As[k4 * 4 + 2][row] = av.z;
            As[k4 * 4 + 3][row] = av.w;
        }
        #pragma unroll
        for (int it = 0; it < 2; it++) {
            int j  = tid + it * 128;
            int kk = j >> 4;
            int n4 = j & 15;
            float4 wv = *(const float4*)(Wl + (kc + kk) * 64 + n4 * 4);
            *(float4*)(&Bs[kk][n4 * 4]) = wv;
        }
        __syncthreads();
        #pragma unroll
        for (int k = 0; k < 16; k++) {
            float a[8];
            *(float4*)(a)     = *(const float4*)(&As[k][ty * 8]);
            *(float4*)(a + 4) = *(const float4*)(&As[k][ty * 8 + 4]);
            unsigned long long b2[4];
            #pragma unroll
            for (int j = 0; j < 4; j++)
                b2[j] = *(const unsigned long long*)(&Bs[k][tx * 8 + j * 2]);
            #pragma unroll
            for (int i = 0; i < 8; i++) {
                unsigned long long av;
                PACK_DUP(av, a[i]);
                #pragma unroll
                for (int j = 0; j < 4; j++)
                    FMA2(acc2[i][j], av, b2[j], acc2[i][j]);
            }
        }
        __syncthreads();
    }
    float bb[8];
    #pragma unroll
    for (int j = 0; j < 8; j++) bb[j] = bl[tx * 8 + j];
    #pragma unroll
    for (int i = 0; i < 8; i++) {
        int gr = m0 + ty * 8 + i;
        if (gr < N_NODES) {
            float o[8];
            #pragma unroll
            for (int j = 0; j < 4; j++)
                UNPACK2(o[2 * j], o[2 * j + 1], acc2[i][j]);
            float4 o0 = make_float4(o[0] + bb[0], o[1] + bb[1], o[2] + bb[2], o[3] + bb[3]);
            float4 o1 = make_float4(o[4] + bb[4], o[5] + bb[5], o[6] + bb[6], o[7] + bb[7]);
            *(float4*)(out + gr * 64 + tx * 8)     = o0;
            *(float4*)(out + gr * 64 + tx * 8 + 4) = o1;
        }
    }
}

// ---------------- launch ----------------
extern "C" void kernel_launch(void* const* d_in, const int* in_sizes, int n_in,
                              void* d_out, int out_size) {
    const float* x   = (const float*)d_in[0];
    const int*   y   = (const int*)d_in[1];
    const int*   ei  = (const int*)d_in[2];
    const float* emb = (const float*)d_in[3];
    const float* Wq = (const float*)d_in[4];  const float* bq = (const float*)d_in[5];
    const float* Wk = (const float*)d_in[6];  const float* bk = (const float*)d_in[7];
    const float* Wv = (const float*)d_in[8];  const float* bv = (const float*)d_in[9];
    const float* Ws = (const float*)d_in[10]; const float* bs = (const float*)d_in[11];
    const float* Wl = (const float*)d_in[12]; const float* bl = (const float*)d_in[13];
    float* out = (float*)d_out;

    k_init      <<<5168, 256>>>(x, y, emb, Wq, Wk, Wv, Ws);
    k_hist      <<<(E_EDGES + 255) / 256, 256>>>(ei);
    k_scan_local<<<SCAN_BLOCKS, 256>>>();
    k_scan_bsum <<<1, 256>>>();
    k_scan_apply<<<SCAN_BLOCKS, 256>>>();
    k_scatter   <<<(E_EDGES + 255) / 256, 256>>>(ei);
    k_proj      <<<(N_NODES + 127) / 128, 256>>>(bq, bk, bv, bs);
    k_agg       <<<(N_NODES + 7) / 8, 256>>>();
    k_cls       <<<(N_NODES + 127) / 128, 128>>>(Wl, bl, out);
}

// round 13
// speedup vs baseline: 1.3764x; 1.0265x over previous
#include <cuda_runtime.h>
#include <cuda_fp16.h>
#include <cstdint>
#include <math.h>

#define N_NODES 40000
#define E_EDGES 640000
#define F       128
#define HD      128
#define NHEADS  4
#define VOCABV  64
#define SCAN_BLOCKS ((N_NODES + 255) / 256)   // 157
#define ASTR    66

// packed fp32x2 helpers (sm_100a+)
#define FMA2(d, a, b, c) \
    asm("fma.rn.f32x2 %0, %1, %2, %3;" : "=l"(d) : "l"(a), "l"(b), "l"(c))
#define PACK_DUP(d, f) \
    asm("mov.b64 %0, {%1, %1};" : "=l"(d) : "f"(f))
#define UNPACK2(lo, hi, d) \
    asm("mov.b64 {%0, %1}, %2;" : "=f"(lo), "=f"(hi) : "l"(d))

// ---------------- scratch ----------------
__device__ unsigned g_xh [N_NODES * F / 2];   // fp16 pairs of x_y (k-pairs)
__device__ unsigned g_Wh [4 * 64 * 128];      // W fp16 hi, k-major: [w][kp*128+n]
__device__ unsigned g_Wl [4 * 64 * 128];      // W fp16 lo
__device__ float    g_q   [N_NODES * HD];
__device__ unsigned g_kh  [N_NODES * 64];     // k as half2 pairs
__device__ unsigned g_vh  [N_NODES * 64];     // v as half2 pairs
__device__ float    g_skip[N_NODES * HD];
__device__ float    g_feat[N_NODES * HD];
__device__ int   g_cnt [N_NODES];
__device__ int   g_start[N_NODES + 1];
__device__ int   g_cur [N_NODES];
__device__ int   g_sorted[E_EDGES];
__device__ int   g_bsum[SCAN_BLOCKS];

__device__ __forceinline__ unsigned pack_f16(float lo, float hi) {
    unsigned r;
    asm("cvt.rn.f16x2.f32 %0, %1, %2;" : "=r"(r) : "f"(hi), "f"(lo));
    return r;
}

__device__ __forceinline__ void mma_f16(float* d, const unsigned* a, const unsigned* b) {
    asm("mma.sync.aligned.m16n8k16.row.col.f32.f16.f16.f32 "
        "{%0,%1,%2,%3}, {%4,%5,%6,%7}, {%8,%9}, {%0,%1,%2,%3};"
        : "+f"(d[0]), "+f"(d[1]), "+f"(d[2]), "+f"(d[3])
        : "r"(a[0]), "r"(a[1]), "r"(a[2]), "r"(a[3]), "r"(b[0]), "r"(b[1]));
}

// ---------------- K0 fused: x_y split + zero counters + W split ----------------
// block partition: [0,5000) xy, [5000,5040) zero cnt, [5040,5168) wsplit
__global__ void __launch_bounds__(256)
k_init(const float* __restrict__ x, const int* __restrict__ y,
       const float* __restrict__ emb,
       const float* __restrict__ Wq, const float* __restrict__ Wk,
       const float* __restrict__ Wv, const float* __restrict__ Ws) {
    int b = blockIdx.x;
    int tid = threadIdx.x;
    if (b < 5000) {
        int i = b * 256 + tid;                 // float4 index, exactly N*32
        int n  = i >> 5;
        int f4 = i & 31;
        int yv = y[n];
        float4 xv = ((const float4*)x)[i];
        float4 ev = *((const float4*)(emb + yv * F) + f4);
        unsigned h0 = pack_f16(xv.x + ev.x, xv.y + ev.y);
        unsigned h1 = pack_f16(xv.z + ev.z, xv.w + ev.w);
        ((uint2*)g_xh)[i] = make_uint2(h0, h1);
    } else if (b < 5040) {
        int i = (b - 5000) * 256 + tid;
        if (i < N_NODES / 4) ((int4*)g_cnt)[i] = make_int4(0, 0, 0, 0);
    } else {
        int i = (b - 5040) * 256 + tid;        // 4*64*128 = 32768 exactly
        int w   = i >> 13;
        int rem = i & 8191;
        int kp  = rem >> 7;
        int n   = rem & 127;
        const float* W = (w == 0) ? Wq : (w == 1) ? Wk : (w == 2) ? Wv : Ws;
        float w0 = W[(2 * kp)     * 128 + n];
        float w1 = W[(2 * kp + 1) * 128 + n];
        float h0 = __half2float(__float2half_rn(w0));
        float h1 = __half2float(__float2half_rn(w1));
        g_Wh[i] = pack_f16(h0, h1);
        g_Wl[i] = pack_f16(w0 - h0, w1 - h1);
    }
}

// ---------------- CSR pass 1: histogram of dst ----------------
__global__ void k_hist(const int* __restrict__ ei) {
    int i = blockIdx.x * blockDim.x + threadIdx.x;
    if (i < E_EDGES) atomicAdd(&g_cnt[ei[E_EDGES + i]], 1);
}

// ---------------- CSR scans ----------------
__global__ void __launch_bounds__(256)
k_scan_local() {
    __shared__ int ps[256];
    int tid = threadIdx.x;
    int i   = blockIdx.x * 256 + tid;
    int v = (i < N_NODES) ? g_cnt[i] : 0;
    ps[tid] = v;
    __syncthreads();
    #pragma unroll
    for (int d = 1; d < 256; d <<= 1) {
        int t = (tid >= d) ? ps[tid - d] : 0;
        __syncthreads();
        ps[tid] += t;
        __syncthreads();
    }
    if (i < N_NODES) g_start[i] = ps[tid];
    if (tid == 255) g_bsum[blockIdx.x] = ps[255];
}

__global__ void __launch_bounds__(256)
k_scan_bsum() {
    __shared__ int ps[256];
    int tid = threadIdx.x;
    int v = (tid < SCAN_BLOCKS) ? g_bsum[tid] : 0;
    ps[tid] = v;
    __syncthreads();
    #pragma unroll
    for (int d = 1; d < 256; d <<= 1) {
        int t = (tid >= d) ? ps[tid - d] : 0;
        __syncthreads();
        ps[tid] += t;
        __syncthreads();
    }
    if (tid < SCAN_BLOCKS) g_bsum[tid] = ps[tid] - v;
}

__global__ void __launch_bounds__(256)
k_scan_apply() {
    int i = blockIdx.x * 256 + threadIdx.x;
    if (i >= N_NODES) return;
    int ex = g_start[i] - g_cnt[i] + g_bsum[blockIdx.x];
    g_start[i] = ex;
    g_cur[i]   = ex;
    if (i == 0) g_start[N_NODES] = E_EDGES;
}

// ---------------- CSR scatter ----------------
__global__ void k_scatter(const int* __restrict__ ei) {
    int i = blockIdx.x * blockDim.x + threadIdx.x;
    if (i >= E_EDGES) return;
    int src = ei[i];
    int dst = ei[E_EDGES + i];
    int pos = atomicAdd(&g_cur[dst], 1);
    g_sorted[pos] = src;
}

// ---------------- K1: projection GEMM, fp16 2-term, A resident full-K --------
// grid 313 x 256 threads (8 warps = 4m x 2n); loops y=0..3 inside; B chunk
// double-buffered. k (y=1) and v (y=2) epilogues write fp16 pairs.
__global__ void __launch_bounds__(256, 2)
k_proj(const float* __restrict__ bq, const float* __restrict__ bk,
       const float* __restrict__ bv, const float* __restrict__ bs) {
    __shared__ unsigned Ah[128 * ASTR];      // fp16 pairs, full K
    __shared__ unsigned Bh[2][1152], Bl[2][1152];

    int tid  = threadIdx.x;
    int wid  = tid >> 5, lane = tid & 31;
    int wm   = wid >> 1;            // 0..3 : rows wm*32..+32
    int wn   = wid & 1;             // 0..1 : cols wn*64..+64
    int g    = lane >> 2;           // 0..7
    int tig  = lane & 3;            // 0..3
    int m0   = blockIdx.x * 128;

    // stage full-K A tile once: 8192 words
    #pragma unroll
    for (int t = 0; t < 32; t++) {
        int idx = tid + t * 256;
        int row = idx >> 6, kp = idx & 63;
        int gr  = m0 + row;
        Ah[row * ASTR + kp] = (gr < N_NODES) ? g_xh[gr * 64 + kp] : 0u;
    }
    // stage B chunk (y=0, ck=0) into buf 0
    #pragma unroll
    for (int t = 0; t < 4; t++) {
        int idx = tid + t * 256;
        int n = idx & 127, kp = idx >> 7;
        Bh[0][n * 9 + kp] = g_Wh[kp * 128 + n];
        Bl[0][n * 9 + kp] = g_Wl[kp * 128 + n];
    }
    __syncthreads();

    for (int y = 0; y < 4; y++) {
        float C[2][8][4];
        #pragma unroll
        for (int mt = 0; mt < 2; mt++)
            #pragma unroll
            for (int nt = 0; nt < 8; nt++)
                #pragma unroll
                for (int c = 0; c < 4; c++) C[mt][nt][c] = 0.f;

        for (int ck = 0; ck < 8; ck++) {
            int it  = y * 8 + ck;           // global chunk counter 0..31
            int buf = it & 1;
            if (it < 31) {                   // stage next chunk into other buf
                int nit = it + 1;
                int nbuf = buf ^ 1;
                const unsigned* Wh = g_Wh + (nit >> 3) * 8192 + (nit & 7) * 8 * 128;
                const unsigned* Wl = g_Wl + (nit >> 3) * 8192 + (nit & 7) * 8 * 128;
                #pragma unroll
                for (int t = 0; t < 4; t++) {
                    int idx = tid + t * 256;
                    int n = idx & 127, kp = idx >> 7;
                    Bh[nbuf][n * 9 + kp] = Wh[kp * 128 + n];
                    Bl[nbuf][n * 9 + kp] = Wl[kp * 128 + n];
                }
            }
            int ck8 = ck * 8;
            unsigned ah[2][4];
            #pragma unroll
            for (int mt = 0; mt < 2; mt++) {
                int base = wm * 32 + mt * 16;
                ah[mt][0] = Ah[(base + g)     * ASTR + ck8 + tig];
                ah[mt][1] = Ah[(base + g + 8) * ASTR + ck8 + tig];
                ah[mt][2] = Ah[(base + g)     * ASTR + ck8 + tig + 4];
                ah[mt][3] = Ah[(base + g + 8) * ASTR + ck8 + tig + 4];
            }
            #pragma unroll
            for (int term = 0; term < 2; term++) {
                const unsigned* B = term ? Bl[buf] : Bh[buf];
                #pragma unroll
                for (int nt = 0; nt < 8; nt++) {
                    int nb = wn * 64 + nt * 8;
                    unsigned b2[2] = { B[(nb + g) * 9 + tig], B[(nb + g) * 9 + tig + 4] };
                    #pragma unroll
                    for (int mt = 0; mt < 2; mt++)
                        mma_f16(C[mt][nt], ah[mt], b2);
                }
            }
            __syncthreads();
        }

        // epilogue: c0=(g,2tig) c1=(g,2tig+1) c2=(g+8,2tig) c3=(g+8,2tig+1)
        const float* bias = (y == 0) ? bq : (y == 1) ? bk : (y == 2) ? bv : bs;
        #pragma unroll
        for (int nt = 0; nt < 8; nt++) {
            int col = wn * 64 + nt * 8 + 2 * tig;
            float2 b2 = *(const float2*)(bias + col);
            #pragma unroll
            for (int mt = 0; mt < 2; mt++) {
                int r0 = m0 + wm * 32 + mt * 16 + g;
                int r1 = r0 + 8;
                float v00 = C[mt][nt][0] + b2.x, v01 = C[mt][nt][1] + b2.y;
                float v10 = C[mt][nt][2] + b2.x, v11 = C[mt][nt][3] + b2.y;
                if (y == 1 || y == 2) {
                    unsigned* outp = (y == 1) ? g_kh : g_vh;
                    if (r0 < N_NODES) outp[r0 * 64 + (col >> 1)] = pack_f16(v00, v01);
                    if (r1 < N_NODES) outp[r1 * 64 + (col >> 1)] = pack_f16(v10, v11);
                } else {
                    float* outp = (y == 0) ? g_q : g_skip;
                    if (r0 < N_NODES) *(float2*)(outp + r0 * 128 + col) = make_float2(v00, v01);
                    if (r1 < N_NODES) *(float2*)(outp + r1 * 128 + col) = make_float2(v10, v11);
                }
            }
        }
    }
}

// ---------------- K2: CSR aggregation, warp per dst, fp16 k/v gathers --------
__global__ void __launch_bounds__(256)
k_agg(void) {
    int n    = blockIdx.x * 8 + (threadIdx.x >> 5);
    int lane = threadIdx.x & 31;
    if (n >= N_NODES) return;
    int s0 = g_start[n];
    int s1 = g_start[n + 1];

    float4 qv = *(const float4*)(g_q + n * 128 + lane * 4);
    float4 acc = make_float4(0.f, 0.f, 0.f, 0.f);
    float den = 0.f;

    // kc/vc are uint2 of half2 pairs: 4 dims per lane
    #define AGG_STEP(kc, vc) do {                                              \
        float2 k0 = __half22float2(*(const __half2*)&(kc).x);                  \
        float2 k1 = __half22float2(*(const __half2*)&(kc).y);                  \
        float sd = qv.x * k0.x + qv.y * k0.y + qv.z * k1.x + qv.w * k1.y;      \
        sd += __shfl_xor_sync(0xffffffffu, sd, 1);                             \
        sd += __shfl_xor_sync(0xffffffffu, sd, 2);                             \
        sd += __shfl_xor_sync(0xffffffffu, sd, 4);                             \
        float ea = __expf(sd * 0.17677669529663687f);                          \
        den += ea;                                                             \
        float2 v0 = __half22float2(*(const __half2*)&(vc).x);                  \
        float2 v1 = __half22float2(*(const __half2*)&(vc).y);                  \
        acc.x = fmaf(ea, v0.x, acc.x);                                         \
        acc.y = fmaf(ea, v0.y, acc.y);                                         \
        acc.z = fmaf(ea, v1.x, acc.z);                                         \
        acc.w = fmaf(ea, v1.y, acc.w);                                         \
    } while (0)

    int e = s0;
    if (s1 - s0 >= 2) {
        int sA = g_sorted[e], sB = g_sorted[e + 1];
        uint2 kA = *(const uint2*)(g_kh + sA * 64 + lane * 2);
        uint2 vA = *(const uint2*)(g_vh + sA * 64 + lane * 2);
        uint2 kB = *(const uint2*)(g_kh + sB * 64 + lane * 2);
        uint2 vB = *(const uint2*)(g_vh + sB * 64 + lane * 2);
        e += 2;
        while (e + 1 < s1) {
            int sC = g_sorted[e], sD = g_sorted[e + 1];
            uint2 kC = *(const uint2*)(g_kh + sC * 64 + lane * 2);
            uint2 vC = *(const uint2*)(g_vh + sC * 64 + lane * 2);
            uint2 kD = *(const uint2*)(g_kh + sD * 64 + lane * 2);
            uint2 vD = *(const uint2*)(g_vh + sD * 64 + lane * 2);
            AGG_STEP(kA, vA);
            AGG_STEP(kB, vB);
            kA = kC; vA = vC; kB = kD; vB = vD;
            e += 2;
        }
        AGG_STEP(kA, vA);
        AGG_STEP(kB, vB);
    }
    if (e < s1) {
        int s = g_sorted[e];
        uint2 kc = *(const uint2*)(g_kh + s * 64 + lane * 2);
        uint2 vc = *(const uint2*)(g_vh + s * 64 + lane * 2);
        AGG_STEP(kc, vc);
    }

    float inv = (den > 0.f) ? (1.0f / den) : 0.f;
    float4 sk = *(const float4*)(g_skip + n * 128 + lane * 4);
    float4 ft = make_float4(fmaf(acc.x, inv, sk.x), fmaf(acc.y, inv, sk.y),
                            fmaf(acc.z, inv, sk.z), fmaf(acc.w, inv, sk.w));
    *(float4*)(g_feat + n * 128 + lane * 4) = ft;
}

// ---------------- K3: classifier out = g_feat @ Wl + bl, f32x2 ----------------
__global__ void __launch_bounds__(128, 4)
k_cls(const float* __restrict__ Wl, const float* __restrict__ bl,
      float* __restrict__ out) {
    __shared__ float As[16][132];
    __shared__ float Bs[16][68];
    int tid = threadIdx.x;
    int m0  = blockIdx.x * 128;
    int ty  = tid >> 3;
    int tx  = tid & 7;

    unsigned long long acc2[8][4];
    #pragma unroll
    for (int i = 0; i < 8; i++)
        #pragma unroll
        for (int j = 0; j < 4; j++) acc2[i][j] = 0ULL;

    for (int kc = 0; kc < 128; kc += 16) {
        #pragma unroll
        for (int it = 0; it < 4; it++) {
            int j   = tid + it * 128;
            int row = j >> 2;
            int k4  = j & 3;
            int gr  = m0 + row;
            float4 av = make_float4(0.f, 0.f, 0.f, 0.f);
            if (gr < N_NODES)
                av = *(const float4*)(g_feat + gr * 128 + kc + k4 * 4);
            As[k4 * 4 + 0][row] = av.x;
            As[k4 * 4 + 1][row] = av.y;
            As[k4 * 4 + 2][row] = av.z;
            As[k4 * 4 + 3][row] = av.w;
        }
        #pragma unroll
        for (int it = 0; it < 2; it++) {
            int j  = tid + it * 128;
            int kk = j >> 4;
            int n4 = j & 15;
            float4 wv = *(const float4*)(Wl + (kc + kk) * 64 + n4 * 4);
            *(float4*)(&Bs[kk][n4 * 4]) = wv;
        }
        __syncthreads();
        #pragma unroll
        for (int k = 0; k < 16; k++) {
            float a[8];
            *(float4*)(a)     = *(const float4*)(&As[k][ty * 8]);
            *(float4*)(a + 4) = *(const float4*)(&As[k][ty * 8 + 4]);
            unsigned long long b2[4];
            #pragma unroll
            for (int j = 0; j < 4; j++)
                b2[j] = *(const unsigned long long*)(&Bs[k][tx * 8 + j * 2]);
            #pragma unroll
            for (int i = 0; i < 8; i++) {
                unsigned long long av;
                PACK_DUP(av, a[i]);
                #pragma unroll
                for (int j = 0; j < 4; j++)
                    FMA2(acc2[i][j], av, b2[j], acc2[i][j]);
            }
        }
        __syncthreads();
    }
    float bb[8];
    #pragma unroll
    for (int j = 0; j < 8; j++) bb[j] = bl[tx * 8 + j];
    #pragma unroll
    for (int i = 0; i < 8; i++) {
        int gr = m0 + ty * 8 + i;
        if (gr < N_NODES) {
            float o[8];
            #pragma unroll
            for (int j = 0; j < 4; j++)
                UNPACK2(o[2 * j], o[2 * j + 1], acc2[i][j]);
            float4 o0 = make_float4(o[0] + bb[0], o[1] + bb[1], o[2] + bb[2], o[3] + bb[3]);
            float4 o1 = make_float4(o[4] + bb[4], o[5] + bb[5], o[6] + bb[6], o[7] + bb[7]);
            *(float4*)(out + gr * 64 + tx * 8)     = o0;
            *(float4*)(out + gr * 64 + tx * 8 + 4) = o1;
        }
    }
}

// ---------------- launch ----------------
extern "C" void kernel_launch(void* const* d_in, const int* in_sizes, int n_in,
                              void* d_out, int out_size) {
    const float* x   = (const float*)d_in[0];
    const int*   y   = (const int*)d_in[1];
    const int*   ei  = (const int*)d_in[2];
    const float* emb = (const float*)d_in[3];
    const float* Wq = (const float*)d_in[4];  const float* bq = (const float*)d_in[5];
    const float* Wk = (const float*)d_in[6];  const float* bk = (const float*)d_in[7];
    const float* Wv = (const float*)d_in[8];  const float* bv = (const float*)d_in[9];
    const float* Ws = (const float*)d_in[10]; const float* bs = (const float*)d_in[11];
    const float* Wl = (const float*)d_in[12]; const float* bl = (const float*)d_in[13];
    float* out = (float*)d_out;

    k_init      <<<5168, 256>>>(x, y, emb, Wq, Wk, Wv, Ws);
    k_hist      <<<(E_EDGES + 255) / 256, 256>>>(ei);
    k_scan_local<<<SCAN_BLOCKS, 256>>>();
    k_scan_bsum <<<1, 256>>>();
    k_scan_apply<<<SCAN_BLOCKS, 256>>>();
    k_scatter   <<<(E_EDGES + 255) / 256, 256>>>(ei);
    k_proj      <<<(N_NODES + 127) / 128, 256>>>(bq, bk, bv, bs);
    k_agg       <<<(N_NODES + 7) / 8, 256>>>();
    k_cls       <<<(N_NODES + 127) / 128, 128>>>(Wl, bl, out);
}

// round 14
// speedup vs baseline: 1.3883x; 1.0086x over previous
#include <cuda_runtime.h>
#include <cuda_fp16.h>
#include <cstdint>
#include <math.h>

#define N_NODES 40000
#define E_EDGES 640000
#define F       128
#define HD      128
#define NHEADS  4
#define VOCABV  64
#define SCAN_BLOCKS ((N_NODES + 255) / 256)   // 157
#define ASTR    66

// packed fp32x2 helpers (sm_100a+)
#define FMA2(d, a, b, c) \
    asm("fma.rn.f32x2 %0, %1, %2, %3;" : "=l"(d) : "l"(a), "l"(b), "l"(c))
#define PACK_DUP(d, f) \
    asm("mov.b64 %0, {%1, %1};" : "=l"(d) : "f"(f))
#define UNPACK2(lo, hi, d) \
    asm("mov.b64 {%0, %1}, %2;" : "=f"(lo), "=f"(hi) : "l"(d))

// ---------------- scratch ----------------
__device__ unsigned g_xh [N_NODES * F / 2];   // fp16 pairs of x_y (k-pairs)
__device__ unsigned g_Wh [4 * 64 * 128];      // W fp16 hi, k-major: [w][kp*128+n]
__device__ unsigned g_Wl [4 * 64 * 128];      // W fp16 lo
__device__ float    g_q   [N_NODES * HD];
__device__ unsigned g_kh  [N_NODES * 64];     // k as half2 pairs
__device__ unsigned g_vh  [N_NODES * 64];     // v as half2 pairs
__device__ float    g_skip[N_NODES * HD];
__device__ float    g_feat[N_NODES * HD];
__device__ int   g_cnt [N_NODES];
__device__ int   g_start[N_NODES + 1];
__device__ int   g_cur [N_NODES];
__device__ int   g_sorted[E_EDGES];
__device__ int   g_bsum[SCAN_BLOCKS];

__device__ __forceinline__ unsigned pack_f16(float lo, float hi) {
    unsigned r;
    asm("cvt.rn.f16x2.f32 %0, %1, %2;" : "=r"(r) : "f"(hi), "f"(lo));
    return r;
}

__device__ __forceinline__ void mma_f16(float* d, const unsigned* a, const unsigned* b) {
    asm("mma.sync.aligned.m16n8k16.row.col.f32.f16.f16.f32 "
        "{%0,%1,%2,%3}, {%4,%5,%6,%7}, {%8,%9}, {%0,%1,%2,%3};"
        : "+f"(d[0]), "+f"(d[1]), "+f"(d[2]), "+f"(d[3])
        : "r"(a[0]), "r"(a[1]), "r"(a[2]), "r"(a[3]), "r"(b[0]), "r"(b[1]));
}

// ---------------- K0 fused: x_y split + zero counters + W split ----------------
// block partition: [0,5000) xy, [5000,5040) zero cnt, [5040,5168) wsplit
__global__ void __launch_bounds__(256)
k_init(const float* __restrict__ x, const int* __restrict__ y,
       const float* __restrict__ emb,
       const float* __restrict__ Wq, const float* __restrict__ Wk,
       const float* __restrict__ Wv, const float* __restrict__ Ws) {
    int b = blockIdx.x;
    int tid = threadIdx.x;
    if (b < 5000) {
        int i = b * 256 + tid;                 // float4 index, exactly N*32
        int n  = i >> 5;
        int f4 = i & 31;
        int yv = y[n];
        float4 xv = ((const float4*)x)[i];
        float4 ev = *((const float4*)(emb + yv * F) + f4);
        unsigned h0 = pack_f16(xv.x + ev.x, xv.y + ev.y);
        unsigned h1 = pack_f16(xv.z + ev.z, xv.w + ev.w);
        ((uint2*)g_xh)[i] = make_uint2(h0, h1);
    } else if (b < 5040) {
        int i = (b - 5000) * 256 + tid;
        if (i < N_NODES / 4) ((int4*)g_cnt)[i] = make_int4(0, 0, 0, 0);
    } else {
        int i = (b - 5040) * 256 + tid;        // 4*64*128 = 32768 exactly
        int w   = i >> 13;
        int rem = i & 8191;
        int kp  = rem >> 7;
        int n   = rem & 127;
        const float* W = (w == 0) ? Wq : (w == 1) ? Wk : (w == 2) ? Wv : Ws;
        float w0 = W[(2 * kp)     * 128 + n];
        float w1 = W[(2 * kp + 1) * 128 + n];
        float h0 = __half2float(__float2half_rn(w0));
        float h1 = __half2float(__float2half_rn(w1));
        g_Wh[i] = pack_f16(h0, h1);
        g_Wl[i] = pack_f16(w0 - h0, w1 - h1);
    }
}

// ---------------- CSR pass 1: histogram of dst ----------------
__global__ void k_hist(const int* __restrict__ ei) {
    int i = blockIdx.x * blockDim.x + threadIdx.x;
    if (i < E_EDGES) atomicAdd(&g_cnt[ei[E_EDGES + i]], 1);
}

// ---------------- CSR scan A: per-block inclusive scan + block sums ----------
__global__ void __launch_bounds__(256)
k_scan_local() {
    __shared__ int ps[256];
    int tid = threadIdx.x;
    int i   = blockIdx.x * 256 + tid;
    int v = (i < N_NODES) ? g_cnt[i] : 0;
    ps[tid] = v;
    __syncthreads();
    #pragma unroll
    for (int d = 1; d < 256; d <<= 1) {
        int t = (tid >= d) ? ps[tid - d] : 0;
        __syncthreads();
        ps[tid] += t;
        __syncthreads();
    }
    if (i < N_NODES) g_start[i] = ps[tid];
    if (tid == 255) g_bsum[blockIdx.x] = ps[255];
}

// ---------------- CSR scan B: apply (each block scans the 157 sums itself) ---
__global__ void __launch_bounds__(256)
k_scan_apply() {
    __shared__ int bs[256];
    int tid = threadIdx.x;
    int v = (tid < SCAN_BLOCKS) ? g_bsum[tid] : 0;
    bs[tid] = v;
    __syncthreads();
    #pragma unroll
    for (int d = 1; d < 256; d <<= 1) {
        int t = (tid >= d) ? bs[tid - d] : 0;
        __syncthreads();
        bs[tid] += t;
        __syncthreads();
    }
    int off = (blockIdx.x == 0) ? 0 : bs[blockIdx.x - 1];
    int i = blockIdx.x * 256 + tid;
    if (i >= N_NODES) return;
    int ex = g_start[i] - g_cnt[i] + off;
    g_start[i] = ex;
    g_cur[i]   = ex;
    if (i == 0) g_start[N_NODES] = E_EDGES;
}

// ---------------- CSR scatter ----------------
__global__ void k_scatter(const int* __restrict__ ei) {
    int i = blockIdx.x * blockDim.x + threadIdx.x;
    if (i >= E_EDGES) return;
    int src = ei[i];
    int dst = ei[E_EDGES + i];
    int pos = atomicAdd(&g_cur[dst], 1);
    g_sorted[pos] = src;
}

// ---------------- K1: projection GEMM, fp16 2-term, A resident full-K --------
__global__ void __launch_bounds__(256, 2)
k_proj(const float* __restrict__ bq, const float* __restrict__ bk,
       const float* __restrict__ bv, const float* __restrict__ bs) {
    __shared__ unsigned Ah[128 * ASTR];      // fp16 pairs, full K
    __shared__ unsigned Bh[2][1152], Bl[2][1152];

    int tid  = threadIdx.x;
    int wid  = tid >> 5, lane = tid & 31;
    int wm   = wid >> 1;
    int wn   = wid & 1;
    int g    = lane >> 2;
    int tig  = lane & 3;
    int m0   = blockIdx.x * 128;

    #pragma unroll
    for (int t = 0; t < 32; t++) {
        int idx = tid + t * 256;
        int row = idx >> 6, kp = idx & 63;
        int gr  = m0 + row;
        Ah[row * ASTR + kp] = (gr < N_NODES) ? g_xh[gr * 64 + kp] : 0u;
    }
    #pragma unroll
    for (int t = 0; t < 4; t++) {
        int idx = tid + t * 256;
        int n = idx & 127, kp = idx >> 7;
        Bh[0][n * 9 + kp] = g_Wh[kp * 128 + n];
        Bl[0][n * 9 + kp] = g_Wl[kp * 128 + n];
    }
    __syncthreads();

    for (int y = 0; y < 4; y++) {
        float C[2][8][4];
        #pragma unroll
        for (int mt = 0; mt < 2; mt++)
            #pragma unroll
            for (int nt = 0; nt < 8; nt++)
                #pragma unroll
                for (int c = 0; c < 4; c++) C[mt][nt][c] = 0.f;

        for (int ck = 0; ck < 8; ck++) {
            int it  = y * 8 + ck;
            int buf = it & 1;
            if (it < 31) {
                int nit = it + 1;
                int nbuf = buf ^ 1;
                const unsigned* Wh = g_Wh + (nit >> 3) * 8192 + (nit & 7) * 8 * 128;
                const unsigned* Wl = g_Wl + (nit >> 3) * 8192 + (nit & 7) * 8 * 128;
                #pragma unroll
                for (int t = 0; t < 4; t++) {
                    int idx = tid + t * 256;
                    int n = idx & 127, kp = idx >> 7;
                    Bh[nbuf][n * 9 + kp] = Wh[kp * 128 + n];
                    Bl[nbuf][n * 9 + kp] = Wl[kp * 128 + n];
                }
            }
            int ck8 = ck * 8;
            unsigned ah[2][4];
            #pragma unroll
            for (int mt = 0; mt < 2; mt++) {
                int base = wm * 32 + mt * 16;
                ah[mt][0] = Ah[(base + g)     * ASTR + ck8 + tig];
                ah[mt][1] = Ah[(base + g + 8) * ASTR + ck8 + tig];
                ah[mt][2] = Ah[(base + g)     * ASTR + ck8 + tig + 4];
                ah[mt][3] = Ah[(base + g + 8) * ASTR + ck8 + tig + 4];
            }
            #pragma unroll
            for (int term = 0; term < 2; term++) {
                const unsigned* B = term ? Bl[buf] : Bh[buf];
                #pragma unroll
                for (int nt = 0; nt < 8; nt++) {
                    int nb = wn * 64 + nt * 8;
                    unsigned b2[2] = { B[(nb + g) * 9 + tig], B[(nb + g) * 9 + tig + 4] };
                    #pragma unroll
                    for (int mt = 0; mt < 2; mt++)
                        mma_f16(C[mt][nt], ah[mt], b2);
                }
            }
            __syncthreads();
        }

        const float* bias = (y == 0) ? bq : (y == 1) ? bk : (y == 2) ? bv : bs;
        #pragma unroll
        for (int nt = 0; nt < 8; nt++) {
            int col = wn * 64 + nt * 8 + 2 * tig;
            float2 b2 = *(const float2*)(bias + col);
            #pragma unroll
            for (int mt = 0; mt < 2; mt++) {
                int r0 = m0 + wm * 32 + mt * 16 + g;
                int r1 = r0 + 8;
                float v00 = C[mt][nt][0] + b2.x, v01 = C[mt][nt][1] + b2.y;
                float v10 = C[mt][nt][2] + b2.x, v11 = C[mt][nt][3] + b2.y;
                if (y == 1 || y == 2) {
                    unsigned* outp = (y == 1) ? g_kh : g_vh;
                    if (r0 < N_NODES) outp[r0 * 64 + (col >> 1)] = pack_f16(v00, v01);
                    if (r1 < N_NODES) outp[r1 * 64 + (col >> 1)] = pack_f16(v10, v11);
                } else {
                    float* outp = (y == 0) ? g_q : g_skip;
                    if (r0 < N_NODES) *(float2*)(outp + r0 * 128 + col) = make_float2(v00, v01);
                    if (r1 < N_NODES) *(float2*)(outp + r1 * 128 + col) = make_float2(v10, v11);
                }
            }
        }
    }
}

// ---------------- K2: CSR aggregation, 2 nodes per warp (16 lanes each) ------
// Each 16-lane group handles one dst node; lane covers 8 dims (uint4 of half2).
// Head = 32 dims = aligned 4-lane group; shfl_xor 1,2 reduces within it.
__global__ void __launch_bounds__(256)
k_agg(void) {
    int warp = blockIdx.x * 8 + (threadIdx.x >> 5);
    int lane = threadIdx.x & 31;
    int half = lane >> 4;          // 0 or 1: which node in the warp
    int gl   = lane & 15;          // 0..15 within the group
    int n = warp * 2 + half;
    if (n >= N_NODES) return;
    int s0 = g_start[n];
    int s1 = g_start[n + 1];

    float q[8];
    *(float4*)(q)     = *(const float4*)(g_q + n * 128 + gl * 8);
    *(float4*)(q + 4) = *(const float4*)(g_q + n * 128 + gl * 8 + 4);

    float acc[8] = {0.f, 0.f, 0.f, 0.f, 0.f, 0.f, 0.f, 0.f};
    float den = 0.f;

    // kc/vc are uint4 of half2 pairs: 8 dims per lane
    #define AGG_STEP(kc, vc) do {                                              \
        float2 kk0 = __half22float2(*(const __half2*)&(kc).x);                 \
        float2 kk1 = __half22float2(*(const __half2*)&(kc).y);                 \
        float2 kk2 = __half22float2(*(const __half2*)&(kc).z);                 \
        float2 kk3 = __half22float2(*(const __half2*)&(kc).w);                 \
        float sd = q[0]*kk0.x + q[1]*kk0.y + q[2]*kk1.x + q[3]*kk1.y           \
                 + q[4]*kk2.x + q[5]*kk2.y + q[6]*kk3.x + q[7]*kk3.y;          \
        sd += __shfl_xor_sync(0xffffffffu, sd, 1);                             \
        sd += __shfl_xor_sync(0xffffffffu, sd, 2);                             \
        float ea = __expf(sd * 0.17677669529663687f);                          \
        den += ea;                                                             \
        float2 vv0 = __half22float2(*(const __half2*)&(vc).x);                 \
        float2 vv1 = __half22float2(*(const __half2*)&(vc).y);                 \
        float2 vv2 = __half22float2(*(const __half2*)&(vc).z);                 \
        float2 vv3 = __half22float2(*(const __half2*)&(vc).w);                 \
        acc[0] = fmaf(ea, vv0.x, acc[0]);                                      \
        acc[1] = fmaf(ea, vv0.y, acc[1]);                                      \
        acc[2] = fmaf(ea, vv1.x, acc[2]);                                      \
        acc[3] = fmaf(ea, vv1.y, acc[3]);                                      \
        acc[4] = fmaf(ea, vv2.x, acc[4]);                                      \
        acc[5] = fmaf(ea, vv2.y, acc[5]);                                      \
        acc[6] = fmaf(ea, vv3.x, acc[6]);                                      \
        acc[7] = fmaf(ea, vv3.y, acc[7]);                                      \
    } while (0)

    int e = s0;
    if (s1 - s0 >= 2) {
        int sA = g_sorted[e], sB = g_sorted[e + 1];
        uint4 kA = *(const uint4*)(g_kh + sA * 64 + gl * 4);
        uint4 vA = *(const uint4*)(g_vh + sA * 64 + gl * 4);
        uint4 kB = *(const uint4*)(g_kh + sB * 64 + gl * 4);
        uint4 vB = *(const uint4*)(g_vh + sB * 64 + gl * 4);
        e += 2;
        while (e + 1 < s1) {
            int sC = g_sorted[e], sD = g_sorted[e + 1];
            uint4 kC = *(const uint4*)(g_kh + sC * 64 + gl * 4);
            uint4 vC = *(const uint4*)(g_vh + sC * 64 + gl * 4);
            uint4 kD = *(const uint4*)(g_kh + sD * 64 + gl * 4);
            uint4 vD = *(const uint4*)(g_vh + sD * 64 + gl * 4);
            AGG_STEP(kA, vA);
            AGG_STEP(kB, vB);
            kA = kC; vA = vC; kB = kD; vB = vD;
            e += 2;
        }
        AGG_STEP(kA, vA);
        AGG_STEP(kB, vB);
    }
    if (e < s1) {
        int s = g_sorted[e];
        uint4 kc = *(const uint4*)(g_kh + s * 64 + gl * 4);
        uint4 vc = *(const uint4*)(g_vh + s * 64 + gl * 4);
        AGG_STEP(kc, vc);
    }

    float inv = (den > 0.f) ? (1.0f / den) : 0.f;
    float4 s0f = *(const float4*)(g_skip + n * 128 + gl * 8);
    float4 s1f = *(const float4*)(g_skip + n * 128 + gl * 8 + 4);
    float4 f0 = make_float4(fmaf(acc[0], inv, s0f.x), fmaf(acc[1], inv, s0f.y),
                            fmaf(acc[2], inv, s0f.z), fmaf(acc[3], inv, s0f.w));
    float4 f1 = make_float4(fmaf(acc[4], inv, s1f.x), fmaf(acc[5], inv, s1f.y),
                            fmaf(acc[6], inv, s1f.z), fmaf(acc[7], inv, s1f.w));
    *(float4*)(g_feat + n * 128 + gl * 8)     = f0;
    *(float4*)(g_feat + n * 128 + gl * 8 + 4) = f1;
}

// ---------------- K3: classifier out = g_feat @ Wl + bl, f32x2 ----------------
__global__ void __launch_bounds__(128, 4)
k_cls(const float* __restrict__ Wl, const float* __restrict__ bl,
      float* __restrict__ out) {
    __shared__ float As[16][132];
    __shared__ float Bs[16][68];
    int tid = threadIdx.x;
    int m0  = blockIdx.x * 128;
    int ty  = tid >> 3;
    int tx  = tid & 7;

    unsigned long long acc2[8][4];
    #pragma unroll
    for (int i = 0; i < 8; i++)
        #pragma unroll
        for (int j = 0; j < 4; j++) acc2[i][j] = 0ULL;

    for (int kc = 0; kc < 128; kc += 16) {
        #pragma unroll
        for (int it = 0; it < 4; it++) {
            int j   = tid + it * 128;
            int row = j >> 2;
            int k4  = j & 3;
            int gr  = m0 + row;
            float4 av = make_float4(0.f, 0.f, 0.f, 0.f);
            if (gr < N_NODES)
                av = *(const float4*)(g_feat + gr * 128 + kc + k4 * 4);
            As[k4 * 4 + 0][row] = av.x;
            As[k4 * 4 + 1][row] = av.y;
            As[k4 * 4 + 2][row] = av.z;
            As[k4 * 4 + 3][row] = av.w;
        }
        #pragma unroll
        for (int it = 0; it < 2; it++) {
            int j  = tid + it * 128;
            int kk = j >> 4;
            int n4 = j & 15;
            float4 wv = *(const float4*)(Wl + (kc + kk) * 64 + n4 * 4);
            *(float4*)(&Bs[kk][n4 * 4]) = wv;
        }
        __syncthreads();
        #pragma unroll
        for (int k = 0; k < 16; k++) {
            float a[8];
            *(float4*)(a)     = *(const float4*)(&As[k][ty * 8]);
            *(float4*)(a + 4) = *(const float4*)(&As[k][ty * 8 + 4]);
            unsigned long long b2[4];
            #pragma unroll
            for (int j = 0; j < 4; j++)
                b2[j] = *(const unsigned long long*)(&Bs[k][tx * 8 + j * 2]);
            #pragma unroll
            for (int i = 0; i < 8; i++) {
                unsigned long long av;
                PACK_DUP(av, a[i]);
                #pragma unroll
                for (int j = 0; j < 4; j++)
                    FMA2(acc2[i][j], av, b2[j], acc2[i][j]);
            }
        }
        __syncthreads();
    }
    float bb[8];
    #pragma unroll
    for (int j = 0; j < 8; j++) bb[j] = bl[tx * 8 + j];
    #pragma unroll
    for (int i = 0; i < 8; i++) {
        int gr = m0 + ty * 8 + i;
        if (gr < N_NODES) {
            float o[8];
            #pragma unroll
            for (int j = 0; j < 4; j++)
                UNPACK2(o[2 * j], o[2 * j + 1], acc2[i][j]);
            float4 o0 = make_float4(o[0] + bb[0], o[1] + bb[1], o[2] + bb[2], o[3] + bb[3]);
            float4 o1 = make_float4(o[4] + bb[4], o[5] + bb[5], o[6] + bb[6], o[7] + bb[7]);
            *(float4*)(out + gr * 64 + tx * 8)     = o0;
            *(float4*)(out + gr * 64 + tx * 8 + 4) = o1;
        }
    }
}

// ---------------- launch ----------------
extern "C" void kernel_launch(void* const* d_in, const int* in_sizes, int n_in,
                              void* d_out, int out_size) {
    const float* x   = (const float*)d_in[0];
    const int*   y   = (const int*)d_in[1];
    const int*   ei  = (const int*)d_in[2];
    const float* emb = (const float*)d_in[3];
    const float* Wq = (const float*)d_in[4];  const float* bq = (const float*)d_in[5];
    const float* Wk = (const float*)d_in[6];  const float* bk = (const float*)d_in[7];
    const float* Wv = (const float*)d_in[8];  const float* bv = (const float*)d_in[9];
    const float* Ws = (const float*)d_in[10]; const float* bs = (const float*)d_in[11];
    const float* Wl = (const float*)d_in[12]; const float* bl = (const float*)d_in[13];
    float* out = (float*)d_out;

    k_init      <<<5168, 256>>>(x, y, emb, Wq, Wk, Wv, Ws);
    k_hist      <<<(E_EDGES + 255) / 256, 256>>>(ei);
    k_scan_local<<<SCAN_BLOCKS, 256>>>();
    k_scan_apply<<<SCAN_BLOCKS, 256>>>();
    k_scatter   <<<(E_EDGES + 255) / 256, 256>>>(ei);
    k_proj      <<<(N_NODES + 127) / 128, 256>>>(bq, bk, bv, bs);
    k_agg       <<<(N_NODES / 2 + 7) / 8, 256>>>();   // 2 nodes per warp
    k_cls       <<<(N_NODES + 127) / 128, 128>>>(Wl, bl, out);
}

// round 15
// speedup vs baseline: 1.5361x; 1.1065x over previous
#include <cuda_runtime.h>
#include <cuda_fp16.h>
#include <cstdint>
#include <math.h>

#define N_NODES 40000
#define E_EDGES 640000
#define F       128
#define HD      128
#define NHEADS  4
#define VOCABV  64
#define SCAN_BLOCKS ((N_NODES + 255) / 256)   // 157
#define ASTR    66

// ---------------- scratch ----------------
__device__ unsigned g_xh  [N_NODES * F / 2];  // fp16 pairs of x_y (k-pairs)
__device__ unsigned g_Wh  [4 * 64 * 128];     // W fp16 hi, k-major: [w][kp*128+n]
__device__ unsigned g_Wl  [4 * 64 * 128];     // W fp16 lo
__device__ unsigned g_Wlh [64 * 64];          // Wl (classifier) fp16 hi, [kp*64+n]
__device__ unsigned g_Wll [64 * 64];          // Wl fp16 lo
__device__ float    g_q   [N_NODES * HD];
__device__ unsigned g_kh  [N_NODES * 64];     // k as half2 pairs
__device__ unsigned g_vh  [N_NODES * 64];     // v as half2 pairs
__device__ float    g_skip[N_NODES * HD];
__device__ unsigned g_fh  [N_NODES * 64];     // feat fp16 hi pairs
__device__ unsigned g_fl  [N_NODES * 64];     // feat fp16 lo pairs
__device__ int   g_cnt [N_NODES];
__device__ int   g_start[N_NODES + 1];
__device__ int   g_cur [N_NODES];
__device__ int   g_sorted[E_EDGES];
__device__ int   g_bsum[SCAN_BLOCKS];

__device__ __forceinline__ unsigned pack_f16(float lo, float hi) {
    unsigned r;
    asm("cvt.rn.f16x2.f32 %0, %1, %2;" : "=r"(r) : "f"(hi), "f"(lo));
    return r;
}

__device__ __forceinline__ void mma_f16(float* d, const unsigned* a, const unsigned* b) {
    asm("mma.sync.aligned.m16n8k16.row.col.f32.f16.f16.f32 "
        "{%0,%1,%2,%3}, {%4,%5,%6,%7}, {%8,%9}, {%0,%1,%2,%3};"
        : "+f"(d[0]), "+f"(d[1]), "+f"(d[2]), "+f"(d[3])
        : "r"(a[0]), "r"(a[1]), "r"(a[2]), "r"(a[3]), "r"(b[0]), "r"(b[1]));
}

// ---------------- K0 fused: x_y split + zero cnt + W split + Wl split --------
// blocks: [0,5000) xy | [5000,5040) zero | [5040,5168) Wqkvs | [5168,5184) Wl
__global__ void __launch_bounds__(256)
k_init(const float* __restrict__ x, const int* __restrict__ y,
       const float* __restrict__ emb,
       const float* __restrict__ Wq, const float* __restrict__ Wk,
       const float* __restrict__ Wv, const float* __restrict__ Ws,
       const float* __restrict__ Wl) {
    int b = blockIdx.x;
    int tid = threadIdx.x;
    if (b < 5000) {
        int i = b * 256 + tid;                 // float4 index, exactly N*32
        int n  = i >> 5;
        int f4 = i & 31;
        int yv = y[n];
        float4 xv = ((const float4*)x)[i];
        float4 ev = *((const float4*)(emb + yv * F) + f4);
        unsigned h0 = pack_f16(xv.x + ev.x, xv.y + ev.y);
        unsigned h1 = pack_f16(xv.z + ev.z, xv.w + ev.w);
        ((uint2*)g_xh)[i] = make_uint2(h0, h1);
    } else if (b < 5040) {
        int i = (b - 5000) * 256 + tid;
        if (i < N_NODES / 4) ((int4*)g_cnt)[i] = make_int4(0, 0, 0, 0);
    } else if (b < 5168) {
        int i = (b - 5040) * 256 + tid;        // 4*64*128 = 32768 exactly
        int w   = i >> 13;
        int rem = i & 8191;
        int kp  = rem >> 7;
        int n   = rem & 127;
        const float* W = (w == 0) ? Wq : (w == 1) ? Wk : (w == 2) ? Wv : Ws;
        float w0 = W[(2 * kp)     * 128 + n];
        float w1 = W[(2 * kp + 1) * 128 + n];
        float h0 = __half2float(__float2half_rn(w0));
        float h1 = __half2float(__float2half_rn(w1));
        g_Wh[i] = pack_f16(h0, h1);
        g_Wl[i] = pack_f16(w0 - h0, w1 - h1);
    } else {
        int i = (b - 5168) * 256 + tid;        // 64*64 = 4096 exactly
        int kp = i >> 6;
        int n  = i & 63;
        float w0 = Wl[(2 * kp)     * 64 + n];
        float w1 = Wl[(2 * kp + 1) * 64 + n];
        float h0 = __half2float(__float2half_rn(w0));
        float h1 = __half2float(__float2half_rn(w1));
        g_Wlh[i] = pack_f16(h0, h1);
        g_Wll[i] = pack_f16(w0 - h0, w1 - h1);
    }
}

// ---------------- CSR pass 1: histogram of dst ----------------
__global__ void k_hist(const int* __restrict__ ei) {
    int i = blockIdx.x * blockDim.x + threadIdx.x;
    if (i < E_EDGES) atomicAdd(&g_cnt[ei[E_EDGES + i]], 1);
}

// ---------------- CSR scan A: per-block inclusive scan + block sums ----------
__global__ void __launch_bounds__(256)
k_scan_local() {
    __shared__ int ps[256];
    int tid = threadIdx.x;
    int i   = blockIdx.x * 256 + tid;
    int v = (i < N_NODES) ? g_cnt[i] : 0;
    ps[tid] = v;
    __syncthreads();
    #pragma unroll
    for (int d = 1; d < 256; d <<= 1) {
        int t = (tid >= d) ? ps[tid - d] : 0;
        __syncthreads();
        ps[tid] += t;
        __syncthreads();
    }
    if (i < N_NODES) g_start[i] = ps[tid];
    if (tid == 255) g_bsum[blockIdx.x] = ps[255];
}

// ---------------- CSR scan B: apply (each block scans the 157 sums itself) ---
__global__ void __launch_bounds__(256)
k_scan_apply() {
    __shared__ int bs[256];
    int tid = threadIdx.x;
    int v = (tid < SCAN_BLOCKS) ? g_bsum[tid] : 0;
    bs[tid] = v;
    __syncthreads();
    #pragma unroll
    for (int d = 1; d < 256; d <<= 1) {
        int t = (tid >= d) ? bs[tid - d] : 0;
        __syncthreads();
        bs[tid] += t;
        __syncthreads();
    }
    int off = (blockIdx.x == 0) ? 0 : bs[blockIdx.x - 1];
    int i = blockIdx.x * 256 + tid;
    if (i >= N_NODES) return;
    int ex = g_start[i] - g_cnt[i] + off;
    g_start[i] = ex;
    g_cur[i]   = ex;
    if (i == 0) g_start[N_NODES] = E_EDGES;
}

// ---------------- CSR scatter ----------------
__global__ void k_scatter(const int* __restrict__ ei) {
    int i = blockIdx.x * blockDim.x + threadIdx.x;
    if (i >= E_EDGES) return;
    int src = ei[i];
    int dst = ei[E_EDGES + i];
    int pos = atomicAdd(&g_cur[dst], 1);
    g_sorted[pos] = src;
}

// ---------------- K1: projection GEMM ----------------
// q/k/v: single-term (x-hi * W-hi). skip: 2-term (x-hi * (W-hi + W-lo)).
__global__ void __launch_bounds__(256, 2)
k_proj(const float* __restrict__ bq, const float* __restrict__ bk,
       const float* __restrict__ bv, const float* __restrict__ bs) {
    __shared__ unsigned Ah[128 * ASTR];      // fp16 pairs, full K
    __shared__ unsigned Bh[2][1152], Bl[2][1152];

    int tid  = threadIdx.x;
    int wid  = tid >> 5, lane = tid & 31;
    int wm   = wid >> 1;
    int wn   = wid & 1;
    int g    = lane >> 2;
    int tig  = lane & 3;
    int m0   = blockIdx.x * 128;

    #pragma unroll
    for (int t = 0; t < 32; t++) {
        int idx = tid + t * 256;
        int row = idx >> 6, kp = idx & 63;
        int gr  = m0 + row;
        Ah[row * ASTR + kp] = (gr < N_NODES) ? g_xh[gr * 64 + kp] : 0u;
    }
    #pragma unroll
    for (int t = 0; t < 4; t++) {
        int idx = tid + t * 256;
        int n = idx & 127, kp = idx >> 7;
        Bh[0][n * 9 + kp] = g_Wh[kp * 128 + n];
    }
    __syncthreads();

    for (int y = 0; y < 4; y++) {
        float C[2][8][4];
        #pragma unroll
        for (int mt = 0; mt < 2; mt++)
            #pragma unroll
            for (int nt = 0; nt < 8; nt++)
                #pragma unroll
                for (int c = 0; c < 4; c++) C[mt][nt][c] = 0.f;

        for (int ck = 0; ck < 8; ck++) {
            int it  = y * 8 + ck;
            int buf = it & 1;
            if (it < 31) {
                int nit = it + 1;
                int nbuf = buf ^ 1;
                int ny = nit >> 3;
                const unsigned* Wh = g_Wh + ny * 8192 + (nit & 7) * 8 * 128;
                #pragma unroll
                for (int t = 0; t < 4; t++) {
                    int idx = tid + t * 256;
                    int n = idx & 127, kp = idx >> 7;
                    Bh[nbuf][n * 9 + kp] = Wh[kp * 128 + n];
                }
                if (ny == 3) {   // skip uses 2 terms: also stage W-lo
                    const unsigned* Wlp = g_Wl + ny * 8192 + (nit & 7) * 8 * 128;
                    #pragma unroll
                    for (int t = 0; t < 4; t++) {
                        int idx = tid + t * 256;
                        int n = idx & 127, kp = idx >> 7;
                        Bl[nbuf][n * 9 + kp] = Wlp[kp * 128 + n];
                    }
                }
            }
            int ck8 = ck * 8;
            unsigned ah[2][4];
            #pragma unroll
            for (int mt = 0; mt < 2; mt++) {
                int base = wm * 32 + mt * 16;
                ah[mt][0] = Ah[(base + g)     * ASTR + ck8 + tig];
                ah[mt][1] = Ah[(base + g + 8) * ASTR + ck8 + tig];
                ah[mt][2] = Ah[(base + g)     * ASTR + ck8 + tig + 4];
                ah[mt][3] = Ah[(base + g + 8) * ASTR + ck8 + tig + 4];
            }
            #pragma unroll
            for (int nt = 0; nt < 8; nt++) {
                int nb = wn * 64 + nt * 8;
                unsigned bh2[2] = { Bh[buf][(nb + g) * 9 + tig], Bh[buf][(nb + g) * 9 + tig + 4] };
                #pragma unroll
                for (int mt = 0; mt < 2; mt++)
                    mma_f16(C[mt][nt], ah[mt], bh2);
                if (y == 3) {
                    unsigned bl2[2] = { Bl[buf][(nb + g) * 9 + tig], Bl[buf][(nb + g) * 9 + tig + 4] };
                    #pragma unroll
                    for (int mt = 0; mt < 2; mt++)
                        mma_f16(C[mt][nt], ah[mt], bl2);
                }
            }
            __syncthreads();
        }

        const float* bias = (y == 0) ? bq : (y == 1) ? bk : (y == 2) ? bv : bs;
        #pragma unroll
        for (int nt = 0; nt < 8; nt++) {
            int col = wn * 64 + nt * 8 + 2 * tig;
            float2 b2 = *(const float2*)(bias + col);
            #pragma unroll
            for (int mt = 0; mt < 2; mt++) {
                int r0 = m0 + wm * 32 + mt * 16 + g;
                int r1 = r0 + 8;
                float v00 = C[mt][nt][0] + b2.x, v01 = C[mt][nt][1] + b2.y;
                float v10 = C[mt][nt][2] + b2.x, v11 = C[mt][nt][3] + b2.y;
                if (y == 1 || y == 2) {
                    unsigned* outp = (y == 1) ? g_kh : g_vh;
                    if (r0 < N_NODES) outp[r0 * 64 + (col >> 1)] = pack_f16(v00, v01);
                    if (r1 < N_NODES) outp[r1 * 64 + (col >> 1)] = pack_f16(v10, v11);
                } else {
                    float* outp = (y == 0) ? g_q : g_skip;
                    if (r0 < N_NODES) *(float2*)(outp + r0 * 128 + col) = make_float2(v00, v01);
                    if (r1 < N_NODES) *(float2*)(outp + r1 * 128 + col) = make_float2(v10, v11);
                }
            }
        }
    }
}

// ---------------- K2: CSR aggregation, 2 nodes per warp; feat -> fp16 hi/lo --
__global__ void __launch_bounds__(256)
k_agg(void) {
    int warp = blockIdx.x * 8 + (threadIdx.x >> 5);
    int lane = threadIdx.x & 31;
    int half = lane >> 4;
    int gl   = lane & 15;
    int n = warp * 2 + half;
    if (n >= N_NODES) return;
    int s0 = g_start[n];
    int s1 = g_start[n + 1];

    float q[8];
    *(float4*)(q)     = *(const float4*)(g_q + n * 128 + gl * 8);
    *(float4*)(q + 4) = *(const float4*)(g_q + n * 128 + gl * 8 + 4);

    float acc[8] = {0.f, 0.f, 0.f, 0.f, 0.f, 0.f, 0.f, 0.f};
    float den = 0.f;

    #define AGG_STEP(kc, vc) do {                                              \
        float2 kk0 = __half22float2(*(const __half2*)&(kc).x);                 \
        float2 kk1 = __half22float2(*(const __half2*)&(kc).y);                 \
        float2 kk2 = __half22float2(*(const __half2*)&(kc).z);                 \
        float2 kk3 = __half22float2(*(const __half2*)&(kc).w);                 \
        float sd = q[0]*kk0.x + q[1]*kk0.y + q[2]*kk1.x + q[3]*kk1.y           \
                 + q[4]*kk2.x + q[5]*kk2.y + q[6]*kk3.x + q[7]*kk3.y;          \
        sd += __shfl_xor_sync(0xffffffffu, sd, 1);                             \
        sd += __shfl_xor_sync(0xffffffffu, sd, 2);                             \
        float ea = __expf(sd * 0.17677669529663687f);                          \
        den += ea;                                                             \
        float2 vv0 = __half22float2(*(const __half2*)&(vc).x);                 \
        float2 vv1 = __half22float2(*(const __half2*)&(vc).y);                 \
        float2 vv2 = __half22float2(*(const __half2*)&(vc).z);                 \
        float2 vv3 = __half22float2(*(const __half2*)&(vc).w);                 \
        acc[0] = fmaf(ea, vv0.x, acc[0]);                                      \
        acc[1] = fmaf(ea, vv0.y, acc[1]);                                      \
        acc[2] = fmaf(ea, vv1.x, acc[2]);                                      \
        acc[3] = fmaf(ea, vv1.y, acc[3]);                                      \
        acc[4] = fmaf(ea, vv2.x, acc[4]);                                      \
        acc[5] = fmaf(ea, vv2.y, acc[5]);                                      \
        acc[6] = fmaf(ea, vv3.x, acc[6]);                                      \
        acc[7] = fmaf(ea, vv3.y, acc[7]);                                      \
    } while (0)

    int e = s0;
    if (s1 - s0 >= 2) {
        int sA = g_sorted[e], sB = g_sorted[e + 1];
        uint4 kA = *(const uint4*)(g_kh + sA * 64 + gl * 4);
        uint4 vA = *(const uint4*)(g_vh + sA * 64 + gl * 4);
        uint4 kB = *(const uint4*)(g_kh + sB * 64 + gl * 4);
        uint4 vB = *(const uint4*)(g_vh + sB * 64 + gl * 4);
        e += 2;
        while (e + 1 < s1) {
            int sC = g_sorted[e], sD = g_sorted[e + 1];
            uint4 kC = *(const uint4*)(g_kh + sC * 64 + gl * 4);
            uint4 vC = *(const uint4*)(g_vh + sC * 64 + gl * 4);
            uint4 kD = *(const uint4*)(g_kh + sD * 64 + gl * 4);
            uint4 vD = *(const uint4*)(g_vh + sD * 64 + gl * 4);
            AGG_STEP(kA, vA);
            AGG_STEP(kB, vB);
            kA = kC; vA = vC; kB = kD; vB = vD;
            e += 2;
        }
        AGG_STEP(kA, vA);
        AGG_STEP(kB, vB);
    }
    if (e < s1) {
        int s = g_sorted[e];
        uint4 kc = *(const uint4*)(g_kh + s * 64 + gl * 4);
        uint4 vc = *(const uint4*)(g_vh + s * 64 + gl * 4);
        AGG_STEP(kc, vc);
    }

    float inv = (den > 0.f) ? (1.0f / den) : 0.f;
    float4 s0f = *(const float4*)(g_skip + n * 128 + gl * 8);
    float4 s1f = *(const float4*)(g_skip + n * 128 + gl * 8 + 4);
    float ft[8];
    ft[0] = fmaf(acc[0], inv, s0f.x); ft[1] = fmaf(acc[1], inv, s0f.y);
    ft[2] = fmaf(acc[2], inv, s0f.z); ft[3] = fmaf(acc[3], inv, s0f.w);
    ft[4] = fmaf(acc[4], inv, s1f.x); ft[5] = fmaf(acc[5], inv, s1f.y);
    ft[6] = fmaf(acc[6], inv, s1f.z); ft[7] = fmaf(acc[7], inv, s1f.w);
    unsigned fh[4], fl[4];
    #pragma unroll
    for (int p = 0; p < 4; p++) {
        float a = ft[2 * p], b = ft[2 * p + 1];
        float ha = __half2float(__float2half_rn(a));
        float hb = __half2float(__float2half_rn(b));
        fh[p] = pack_f16(ha, hb);
        fl[p] = pack_f16(a - ha, b - hb);
    }
    *(uint4*)(g_fh + n * 64 + gl * 4) = make_uint4(fh[0], fh[1], fh[2], fh[3]);
    *(uint4*)(g_fl + n * 64 + gl * 4) = make_uint4(fl[0], fl[1], fl[2], fl[3]);
}

// ---------------- K3: classifier, fp16 3-term MMA ----------------
// out = feat @ Wl + bl.  C = fh*wh + fh*wl + fl*wh  (drop lo*lo).
__global__ void __launch_bounds__(256, 2)
k_cls(const float* __restrict__ bl, float* __restrict__ out) {
    __shared__ unsigned Ah[128 * 9], Al[128 * 9];   // per-chunk A
    __shared__ unsigned Bh[64 * 9],  Bl2[64 * 9];
    int tid  = threadIdx.x;
    int wid  = tid >> 5, lane = tid & 31;
    int wm   = wid >> 1;            // 0..3 : rows wm*32..+32
    int wn   = wid & 1;             // 0..1 : cols wn*32..+32
    int g    = lane >> 2;
    int tig  = lane & 3;
    int m0   = blockIdx.x * 128;

    float C[2][4][4];
    #pragma unroll
    for (int mt = 0; mt < 2; mt++)
        #pragma unroll
        for (int nt = 0; nt < 4; nt++)
            #pragma unroll
            for (int c = 0; c < 4; c++) C[mt][nt][c] = 0.f;

    for (int ck = 0; ck < 8; ck++) {
        __syncthreads();
        // stage A chunk: 128 rows x 8 kpairs, hi + lo
        #pragma unroll
        for (int t = 0; t < 4; t++) {
            int idx = tid + t * 256;
            int row = idx >> 3, kp = idx & 7;
            int gr  = m0 + row;
            unsigned vh = 0u, vl = 0u;
            if (gr < N_NODES) {
                vh = g_fh[gr * 64 + ck * 8 + kp];
                vl = g_fl[gr * 64 + ck * 8 + kp];
            }
            Ah[row * 9 + kp] = vh;
            Al[row * 9 + kp] = vl;
        }
        // stage B chunk: 64 rows x 8 kpairs
        #pragma unroll
        for (int t = 0; t < 2; t++) {
            int idx = tid + t * 256;
            int n = idx & 63, kp = idx >> 6;
            Bh[n * 9 + kp]  = g_Wlh[(ck * 8 + kp) * 64 + n];
            Bl2[n * 9 + kp] = g_Wll[(ck * 8 + kp) * 64 + n];
        }
        __syncthreads();

        unsigned ah[2][4], al[2][4];
        #pragma unroll
        for (int mt = 0; mt < 2; mt++) {
            int base = wm * 32 + mt * 16;
            ah[mt][0] = Ah[(base + g)     * 9 + tig];
            ah[mt][1] = Ah[(base + g + 8) * 9 + tig];
            ah[mt][2] = Ah[(base + g)     * 9 + tig + 4];
            ah[mt][3] = Ah[(base + g + 8) * 9 + tig + 4];
            al[mt][0] = Al[(base + g)     * 9 + tig];
            al[mt][1] = Al[(base + g + 8) * 9 + tig];
            al[mt][2] = Al[(base + g)     * 9 + tig + 4];
            al[mt][3] = Al[(base + g + 8) * 9 + tig + 4];
        }
        #pragma unroll
        for (int nt = 0; nt < 4; nt++) {
            int nb = wn * 32 + nt * 8;
            unsigned bh2[2] = { Bh[(nb + g) * 9 + tig],  Bh[(nb + g) * 9 + tig + 4] };
            unsigned bl2[2] = { Bl2[(nb + g) * 9 + tig], Bl2[(nb + g) * 9 + tig + 4] };
            #pragma unroll
            for (int mt = 0; mt < 2; mt++) {
                mma_f16(C[mt][nt], ah[mt], bh2);
                mma_f16(C[mt][nt], ah[mt], bl2);
                mma_f16(C[mt][nt], al[mt], bh2);
            }
        }
    }

    #pragma unroll
    for (int nt = 0; nt < 4; nt++) {
        int col = wn * 32 + nt * 8 + 2 * tig;
        float2 b2 = *(const float2*)(bl + col);
        #pragma unroll
        for (int mt = 0; mt < 2; mt++) {
            int r0 = m0 + wm * 32 + mt * 16 + g;
            int r1 = r0 + 8;
            if (r0 < N_NODES)
                *(float2*)(out + r0 * 64 + col) =
                    make_float2(C[mt][nt][0] + b2.x, C[mt][nt][1] + b2.y);
            if (r1 < N_NODES)
                *(float2*)(out + r1 * 64 + col) =
                    make_float2(C[mt][nt][2] + b2.x, C[mt][nt][3] + b2.y);
        }
    }
}

// ---------------- launch ----------------
extern "C" void kernel_launch(void* const* d_in, const int* in_sizes, int n_in,
                              void* d_out, int out_size) {
    const float* x   = (const float*)d_in[0];
    const int*   y   = (const int*)d_in[1];
    const int*   ei  = (const int*)d_in[2];
    const float* emb = (const float*)d_in[3];
    const float* Wq = (const float*)d_in[4];  const float* bq = (const float*)d_in[5];
    const float* Wk = (const float*)d_in[6];  const float* bk = (const float*)d_in[7];
    const float* Wv = (const float*)d_in[8];  const float* bv = (const float*)d_in[9];
    const float* Ws = (const float*)d_in[10]; const float* bs = (const float*)d_in[11];
    const float* Wl = (const float*)d_in[12]; const float* bl = (const float*)d_in[13];
    float* out = (float*)d_out;

    k_init      <<<5184, 256>>>(x, y, emb, Wq, Wk, Wv, Ws, Wl);
    k_hist      <<<(E_EDGES + 255) / 256, 256>>>(ei);
    k_scan_local<<<SCAN_BLOCKS, 256>>>();
    k_scan_apply<<<SCAN_BLOCKS, 256>>>();
    k_scatter   <<<(E_EDGES + 255) / 256, 256>>>(ei);
    k_proj      <<<(N_NODES + 127) / 128, 256>>>(bq, bk, bv, bs);
    k_agg       <<<(N_NODES / 2 + 7) / 8, 256>>>();
    k_cls       <<<(N_NODES + 127) / 128, 256>>>(bl, out);
}

// round 16
// speedup vs baseline: 1.5996x; 1.0414x over previous
#include <cuda_runtime.h>
#include <cuda_fp16.h>
#include <cstdint>
#include <math.h>

#define N_NODES 40000
#define E_EDGES 640000
#define F       128
#define HD      128
#define NHEADS  4
#define VOCABV  64
#define SCAN_BLOCKS ((N_NODES + 255) / 256)   // 157
#define ASTR    66

// ---------------- scratch ----------------
__device__ unsigned g_xh  [N_NODES * F / 2];  // fp16 pairs of x_y (k-pairs)
__device__ unsigned g_Wh  [4 * 64 * 128];     // W fp16 hi, k-major: [w][kp*128+n]
__device__ unsigned g_Wlh [64 * 64];          // Wl (classifier) fp16 hi, [kp*64+n]
__device__ unsigned g_Wll [64 * 64];          // Wl fp16 lo
__device__ float    g_q   [N_NODES * HD];
__device__ unsigned g_kh  [N_NODES * 64];     // k as half2 pairs
__device__ unsigned g_vh  [N_NODES * 64];     // v as half2 pairs
__device__ float    g_skip[N_NODES * HD];
__device__ unsigned g_fh  [N_NODES * 64];     // feat fp16 pairs
__device__ int   g_cnt [N_NODES];
__device__ int   g_start[N_NODES + 1];
__device__ int   g_cur [N_NODES];
__device__ int   g_sorted[E_EDGES];
__device__ int   g_bsum[SCAN_BLOCKS];

__device__ __forceinline__ unsigned pack_f16(float lo, float hi) {
    unsigned r;
    asm("cvt.rn.f16x2.f32 %0, %1, %2;" : "=r"(r) : "f"(hi), "f"(lo));
    return r;
}

__device__ __forceinline__ void mma_f16(float* d, const unsigned* a, const unsigned* b) {
    asm("mma.sync.aligned.m16n8k16.row.col.f32.f16.f16.f32 "
        "{%0,%1,%2,%3}, {%4,%5,%6,%7}, {%8,%9}, {%0,%1,%2,%3};"
        : "+f"(d[0]), "+f"(d[1]), "+f"(d[2]), "+f"(d[3])
        : "r"(a[0]), "r"(a[1]), "r"(a[2]), "r"(a[3]), "r"(b[0]), "r"(b[1]));
}

// ---------------- K0 fused: x_y split + zero cnt + W split + Wl split --------
// blocks: [0,5000) xy | [5000,5040) zero | [5040,5168) Wqkvs-hi | [5168,5184) Wl
__global__ void __launch_bounds__(256)
k_init(const float* __restrict__ x, const int* __restrict__ y,
       const float* __restrict__ emb,
       const float* __restrict__ Wq, const float* __restrict__ Wk,
       const float* __restrict__ Wv, const float* __restrict__ Ws,
       const float* __restrict__ Wl) {
    int b = blockIdx.x;
    int tid = threadIdx.x;
    if (b < 5000) {
        int i = b * 256 + tid;                 // float4 index, exactly N*32
        int n  = i >> 5;
        int f4 = i & 31;
        int yv = y[n];
        float4 xv = ((const float4*)x)[i];
        float4 ev = *((const float4*)(emb + yv * F) + f4);
        unsigned h0 = pack_f16(xv.x + ev.x, xv.y + ev.y);
        unsigned h1 = pack_f16(xv.z + ev.z, xv.w + ev.w);
        ((uint2*)g_xh)[i] = make_uint2(h0, h1);
    } else if (b < 5040) {
        int i = (b - 5000) * 256 + tid;
        if (i < N_NODES / 4) ((int4*)g_cnt)[i] = make_int4(0, 0, 0, 0);
    } else if (b < 5168) {
        int i = (b - 5040) * 256 + tid;        // 4*64*128 = 32768 exactly
        int w   = i >> 13;
        int rem = i & 8191;
        int kp  = rem >> 7;
        int n   = rem & 127;
        const float* W = (w == 0) ? Wq : (w == 1) ? Wk : (w == 2) ? Wv : Ws;
        float w0 = W[(2 * kp)     * 128 + n];
        float w1 = W[(2 * kp + 1) * 128 + n];
        g_Wh[i] = pack_f16(w0, w1);
    } else {
        int i = (b - 5168) * 256 + tid;        // 64*64 = 4096 exactly
        int kp = i >> 6;
        int n  = i & 63;
        float w0 = Wl[(2 * kp)     * 64 + n];
        float w1 = Wl[(2 * kp + 1) * 64 + n];
        float h0 = __half2float(__float2half_rn(w0));
        float h1 = __half2float(__float2half_rn(w1));
        g_Wlh[i] = pack_f16(h0, h1);
        g_Wll[i] = pack_f16(w0 - h0, w1 - h1);
    }
}

// ---------------- CSR pass 1: histogram of dst ----------------
__global__ void k_hist(const int* __restrict__ ei) {
    int i = blockIdx.x * blockDim.x + threadIdx.x;
    if (i < E_EDGES) atomicAdd(&g_cnt[ei[E_EDGES + i]], 1);
}

// ---------------- CSR scan A: per-block inclusive scan + block sums ----------
__global__ void __launch_bounds__(256)
k_scan_local() {
    __shared__ int ps[256];
    int tid = threadIdx.x;
    int i   = blockIdx.x * 256 + tid;
    int v = (i < N_NODES) ? g_cnt[i] : 0;
    ps[tid] = v;
    __syncthreads();
    #pragma unroll
    for (int d = 1; d < 256; d <<= 1) {
        int t = (tid >= d) ? ps[tid - d] : 0;
        __syncthreads();
        ps[tid] += t;
        __syncthreads();
    }
    if (i < N_NODES) g_start[i] = ps[tid];
    if (tid == 255) g_bsum[blockIdx.x] = ps[255];
}

// ---------------- CSR scan B: apply (each block scans the 157 sums itself) ---
__global__ void __launch_bounds__(256)
k_scan_apply() {
    __shared__ int bs[256];
    int tid = threadIdx.x;
    int v = (tid < SCAN_BLOCKS) ? g_bsum[tid] : 0;
    bs[tid] = v;
    __syncthreads();
    #pragma unroll
    for (int d = 1; d < 256; d <<= 1) {
        int t = (tid >= d) ? bs[tid - d] : 0;
        __syncthreads();
        bs[tid] += t;
        __syncthreads();
    }
    int off = (blockIdx.x == 0) ? 0 : bs[blockIdx.x - 1];
    int i = blockIdx.x * 256 + tid;
    if (i >= N_NODES) return;
    int ex = g_start[i] - g_cnt[i] + off;
    g_start[i] = ex;
    g_cur[i]   = ex;
    if (i == 0) g_start[N_NODES] = E_EDGES;
}

// ---------------- CSR scatter ----------------
__global__ void k_scatter(const int* __restrict__ ei) {
    int i = blockIdx.x * blockDim.x + threadIdx.x;
    if (i >= E_EDGES) return;
    int src = ei[i];
    int dst = ei[E_EDGES + i];
    int pos = atomicAdd(&g_cur[dst], 1);
    g_sorted[pos] = src;
}

// ---------------- K1: projection GEMM, single-term (x-hi * W-hi) ------------
__global__ void __launch_bounds__(256, 2)
k_proj(const float* __restrict__ bq, const float* __restrict__ bk,
       const float* __restrict__ bv, const float* __restrict__ bs) {
    __shared__ unsigned Ah[128 * ASTR];      // fp16 pairs, full K
    __shared__ unsigned Bh[2][1152];

    int tid  = threadIdx.x;
    int wid  = tid >> 5, lane = tid & 31;
    int wm   = wid >> 1;
    int wn   = wid & 1;
    int g    = lane >> 2;
    int tig  = lane & 3;
    int m0   = blockIdx.x * 128;

    #pragma unroll
    for (int t = 0; t < 32; t++) {
        int idx = tid + t * 256;
        int row = idx >> 6, kp = idx & 63;
        int gr  = m0 + row;
        Ah[row * ASTR + kp] = (gr < N_NODES) ? g_xh[gr * 64 + kp] : 0u;
    }
    #pragma unroll
    for (int t = 0; t < 4; t++) {
        int idx = tid + t * 256;
        int n = idx & 127, kp = idx >> 7;
        Bh[0][n * 9 + kp] = g_Wh[kp * 128 + n];
    }
    __syncthreads();

    for (int y = 0; y < 4; y++) {
        float C[2][8][4];
        #pragma unroll
        for (int mt = 0; mt < 2; mt++)
            #pragma unroll
            for (int nt = 0; nt < 8; nt++)
                #pragma unroll
                for (int c = 0; c < 4; c++) C[mt][nt][c] = 0.f;

        for (int ck = 0; ck < 8; ck++) {
            int it  = y * 8 + ck;
            int buf = it & 1;
            if (it < 31) {
                int nit = it + 1;
                int nbuf = buf ^ 1;
                const unsigned* Wh = g_Wh + (nit >> 3) * 8192 + (nit & 7) * 8 * 128;
                #pragma unroll
                for (int t = 0; t < 4; t++) {
                    int idx = tid + t * 256;
                    int n = idx & 127, kp = idx >> 7;
                    Bh[nbuf][n * 9 + kp] = Wh[kp * 128 + n];
                }
            }
            int ck8 = ck * 8;
            unsigned ah[2][4];
            #pragma unroll
            for (int mt = 0; mt < 2; mt++) {
                int base = wm * 32 + mt * 16;
                ah[mt][0] = Ah[(base + g)     * ASTR + ck8 + tig];
                ah[mt][1] = Ah[(base + g + 8) * ASTR + ck8 + tig];
                ah[mt][2] = Ah[(base + g)     * ASTR + ck8 + tig + 4];
                ah[mt][3] = Ah[(base + g + 8) * ASTR + ck8 + tig + 4];
            }
            #pragma unroll
            for (int nt = 0; nt < 8; nt++) {
                int nb = wn * 64 + nt * 8;
                unsigned bh2[2] = { Bh[buf][(nb + g) * 9 + tig], Bh[buf][(nb + g) * 9 + tig + 4] };
                #pragma unroll
                for (int mt = 0; mt < 2; mt++)
                    mma_f16(C[mt][nt], ah[mt], bh2);
            }
            __syncthreads();
        }

        const float* bias = (y == 0) ? bq : (y == 1) ? bk : (y == 2) ? bv : bs;
        #pragma unroll
        for (int nt = 0; nt < 8; nt++) {
            int col = wn * 64 + nt * 8 + 2 * tig;
            float2 b2 = *(const float2*)(bias + col);
            #pragma unroll
            for (int mt = 0; mt < 2; mt++) {
                int r0 = m0 + wm * 32 + mt * 16 + g;
                int r1 = r0 + 8;
                float v00 = C[mt][nt][0] + b2.x, v01 = C[mt][nt][1] + b2.y;
                float v10 = C[mt][nt][2] + b2.x, v11 = C[mt][nt][3] + b2.y;
                if (y == 1 || y == 2) {
                    unsigned* outp = (y == 1) ? g_kh : g_vh;
                    if (r0 < N_NODES) outp[r0 * 64 + (col >> 1)] = pack_f16(v00, v01);
                    if (r1 < N_NODES) outp[r1 * 64 + (col >> 1)] = pack_f16(v10, v11);
                } else {
                    float* outp = (y == 0) ? g_q : g_skip;
                    if (r0 < N_NODES) *(float2*)(outp + r0 * 128 + col) = make_float2(v00, v01);
                    if (r1 < N_NODES) *(float2*)(outp + r1 * 128 + col) = make_float2(v10, v11);
                }
            }
        }
    }
}

// ---------------- K2: CSR aggregation, 2 nodes per warp; feat -> fp16 --------
__global__ void __launch_bounds__(256)
k_agg(void) {
    int warp = blockIdx.x * 8 + (threadIdx.x >> 5);
    int lane = threadIdx.x & 31;
    int half = lane >> 4;
    int gl   = lane & 15;
    int n = warp * 2 + half;
    if (n >= N_NODES) return;
    int s0 = g_start[n];
    int s1 = g_start[n + 1];

    float q[8];
    *(float4*)(q)     = *(const float4*)(g_q + n * 128 + gl * 8);
    *(float4*)(q + 4) = *(const float4*)(g_q + n * 128 + gl * 8 + 4);

    float acc[8] = {0.f, 0.f, 0.f, 0.f, 0.f, 0.f, 0.f, 0.f};
    float den = 0.f;

    #define AGG_STEP(kc, vc) do {                                              \
        float2 kk0 = __half22float2(*(const __half2*)&(kc).x);                 \
        float2 kk1 = __half22float2(*(const __half2*)&(kc).y);                 \
        float2 kk2 = __half22float2(*(const __half2*)&(kc).z);                 \
        float2 kk3 = __half22float2(*(const __half2*)&(kc).w);                 \
        float sd = q[0]*kk0.x + q[1]*kk0.y + q[2]*kk1.x + q[3]*kk1.y           \
                 + q[4]*kk2.x + q[5]*kk2.y + q[6]*kk3.x + q[7]*kk3.y;          \
        sd += __shfl_xor_sync(0xffffffffu, sd, 1);                             \
        sd += __shfl_xor_sync(0xffffffffu, sd, 2);                             \
        float ea = __expf(sd * 0.17677669529663687f);                          \
        den += ea;                                                             \
        float2 vv0 = __half22float2(*(const __half2*)&(vc).x);                 \
        float2 vv1 = __half22float2(*(const __half2*)&(vc).y);                 \
        float2 vv2 = __half22float2(*(const __half2*)&(vc).z);                 \
        float2 vv3 = __half22float2(*(const __half2*)&(vc).w);                 \
        acc[0] = fmaf(ea, vv0.x, acc[0]);                                      \
        acc[1] = fmaf(ea, vv0.y, acc[1]);                                      \
        acc[2] = fmaf(ea, vv1.x, acc[2]);                                      \
        acc[3] = fmaf(ea, vv1.y, acc[3]);                                      \
        acc[4] = fmaf(ea, vv2.x, acc[4]);                                      \
        acc[5] = fmaf(ea, vv2.y, acc[5]);                                      \
        acc[6] = fmaf(ea, vv3.x, acc[6]);                                      \
        acc[7] = fmaf(ea, vv3.y, acc[7]);                                      \
    } while (0)

    int e = s0;
    if (s1 - s0 >= 2) {
        int sA = g_sorted[e], sB = g_sorted[e + 1];
        uint4 kA = *(const uint4*)(g_kh + sA * 64 + gl * 4);
        uint4 vA = *(const uint4*)(g_vh + sA * 64 + gl * 4);
        uint4 kB = *(const uint4*)(g_kh + sB * 64 + gl * 4);
        uint4 vB = *(const uint4*)(g_vh + sB * 64 + gl * 4);
        e += 2;
        while (e + 1 < s1) {
            int sC = g_sorted[e], sD = g_sorted[e + 1];
            uint4 kC = *(const uint4*)(g_kh + sC * 64 + gl * 4);
            uint4 vC = *(const uint4*)(g_vh + sC * 64 + gl * 4);
            uint4 kD = *(const uint4*)(g_kh + sD * 64 + gl * 4);
            uint4 vD = *(const uint4*)(g_vh + sD * 64 + gl * 4);
            AGG_STEP(kA, vA);
            AGG_STEP(kB, vB);
            kA = kC; vA = vC; kB = kD; vB = vD;
            e += 2;
        }
        AGG_STEP(kA, vA);
        AGG_STEP(kB, vB);
    }
    if (e < s1) {
        int s = g_sorted[e];
        uint4 kc = *(const uint4*)(g_kh + s * 64 + gl * 4);
        uint4 vc = *(const uint4*)(g_vh + s * 64 + gl * 4);
        AGG_STEP(kc, vc);
    }

    float inv = (den > 0.f) ? (1.0f / den) : 0.f;
    float4 s0f = *(const float4*)(g_skip + n * 128 + gl * 8);
    float4 s1f = *(const float4*)(g_skip + n * 128 + gl * 8 + 4);
    unsigned fh[4];
    fh[0] = pack_f16(fmaf(acc[0], inv, s0f.x), fmaf(acc[1], inv, s0f.y));
    fh[1] = pack_f16(fmaf(acc[2], inv, s0f.z), fmaf(acc[3], inv, s0f.w));
    fh[2] = pack_f16(fmaf(acc[4], inv, s1f.x), fmaf(acc[5], inv, s1f.y));
    fh[3] = pack_f16(fmaf(acc[6], inv, s1f.z), fmaf(acc[7], inv, s1f.w));
    *(uint4*)(g_fh + n * 64 + gl * 4) = make_uint4(fh[0], fh[1], fh[2], fh[3]);
}

// ---------------- K3: classifier, fp16 2-term MMA ----------------
// out = feat @ Wl + bl.  C = fh*wh + fh*wl.
__global__ void __launch_bounds__(256, 2)
k_cls(const float* __restrict__ bl, float* __restrict__ out) {
    __shared__ unsigned Ah[128 * 9];
    __shared__ unsigned Bh[64 * 9], Bl2[64 * 9];
    int tid  = threadIdx.x;
    int wid  = tid >> 5, lane = tid & 31;
    int wm   = wid >> 1;            // 0..3 : rows wm*32..+32
    int wn   = wid & 1;             // 0..1 : cols wn*32..+32
    int g    = lane >> 2;
    int tig  = lane & 3;
    int m0   = blockIdx.x * 128;

    float C[2][4][4];
    #pragma unroll
    for (int mt = 0; mt < 2; mt++)
        #pragma unroll
        for (int nt = 0; nt < 4; nt++)
            #pragma unroll
            for (int c = 0; c < 4; c++) C[mt][nt][c] = 0.f;

    for (int ck = 0; ck < 8; ck++) {
        __syncthreads();
        #pragma unroll
        for (int t = 0; t < 4; t++) {
            int idx = tid + t * 256;
            int row = idx >> 3, kp = idx & 7;
            int gr  = m0 + row;
            Ah[row * 9 + kp] = (gr < N_NODES) ? g_fh[gr * 64 + ck * 8 + kp] : 0u;
        }
        #pragma unroll
        for (int t = 0; t < 2; t++) {
            int idx = tid + t * 256;
            int n = idx & 63, kp = idx >> 6;
            Bh[n * 9 + kp]  = g_Wlh[(ck * 8 + kp) * 64 + n];
            Bl2[n * 9 + kp] = g_Wll[(ck * 8 + kp) * 64 + n];
        }
        __syncthreads();

        unsigned ah[2][4];
        #pragma unroll
        for (int mt = 0; mt < 2; mt++) {
            int base = wm * 32 + mt * 16;
            ah[mt][0] = Ah[(base + g)     * 9 + tig];
            ah[mt][1] = Ah[(base + g + 8) * 9 + tig];
            ah[mt][2] = Ah[(base + g)     * 9 + tig + 4];
            ah[mt][3] = Ah[(base + g + 8) * 9 + tig + 4];
        }
        #pragma unroll
        for (int nt = 0; nt < 4; nt++) {
            int nb = wn * 32 + nt * 8;
            unsigned bh2[2] = { Bh[(nb + g) * 9 + tig],  Bh[(nb + g) * 9 + tig + 4] };
            unsigned bl2[2] = { Bl2[(nb + g) * 9 + tig], Bl2[(nb + g) * 9 + tig + 4] };
            #pragma unroll
            for (int mt = 0; mt < 2; mt++) {
                mma_f16(C[mt][nt], ah[mt], bh2);
                mma_f16(C[mt][nt], ah[mt], bl2);
            }
        }
    }

    #pragma unroll
    for (int nt = 0; nt < 4; nt++) {
        int col = wn * 32 + nt * 8 + 2 * tig;
        float2 b2 = *(const float2*)(bl + col);
        #pragma unroll
        for (int mt = 0; mt < 2; mt++) {
            int r0 = m0 + wm * 32 + mt * 16 + g;
            int r1 = r0 + 8;
            if (r0 < N_NODES)
                *(float2*)(out + r0 * 64 + col) =
                    make_float2(C[mt][nt][0] + b2.x, C[mt][nt][1] + b2.y);
            if (r1 < N_NODES)
                *(float2*)(out + r1 * 64 + col) =
                    make_float2(C[mt][nt][2] + b2.x, C[mt][nt][3] + b2.y);
        }
    }
}

// ---------------- launch ----------------
extern "C" void kernel_launch(void* const* d_in, const int* in_sizes, int n_in,
                              void* d_out, int out_size) {
    const float* x   = (const float*)d_in[0];
    const int*   y   = (const int*)d_in[1];
    const int*   ei  = (const int*)d_in[2];
    const float* emb = (const float*)d_in[3];
    const float* Wq = (const float*)d_in[4];  const float* bq = (const float*)d_in[5];
    const float* Wk = (const float*)d_in[6];  const float* bk = (const float*)d_in[7];
    const float* Wv = (const float*)d_in[8];  const float* bv = (const float*)d_in[9];
    const float* Ws = (const float*)d_in[10]; const float* bs = (const float*)d_in[11];
    const float* Wl = (const float*)d_in[12]; const float* bl = (const float*)d_in[13];
    float* out = (float*)d_out;

    k_init      <<<5184, 256>>>(x, y, emb, Wq, Wk, Wv, Ws, Wl);
    k_hist      <<<(E_EDGES + 255) / 256, 256>>>(ei);
    k_scan_local<<<SCAN_BLOCKS, 256>>>();
    k_scan_apply<<<SCAN_BLOCKS, 256>>>();
    k_scatter   <<<(E_EDGES + 255) / 256, 256>>>(ei);
    k_proj      <<<(N_NODES + 127) / 128, 256>>>(bq, bk, bv, bs);
    k_agg       <<<(N_NODES / 2 + 7) / 8, 256>>>();
    k_cls       <<<(N_NODES + 127) / 128, 256>>>(bl, out);
}

// round 17
// speedup vs baseline: 1.8996x; 1.1875x over previous
#include <cuda_runtime.h>
#include <cuda_fp16.h>
#include <cstdint>
#include <math.h>

#define N_NODES 40000
#define E_EDGES 640000
#define F       128
#define HD      128
#define NHEADS  4
#define VOCABV  64
#define SCAN_BLOCKS ((N_NODES + 255) / 256)   // 157
#define ASTR    66
#define PROJ_BLOCKS ((N_NODES + 127) / 128)   // 313
#define EDGE_BLOCKS ((E_EDGES + 255) / 256)   // 2500

// ---------------- scratch ----------------
__device__ unsigned g_xh  [N_NODES * F / 2];  // fp16 pairs of x_y (k-pairs)
__device__ unsigned g_Wh  [4 * 64 * 128];     // W fp16, k-major: [w][kp*128+n]
__device__ unsigned g_Wlh [64 * 64];          // Wl (classifier) fp16 hi, [kp*64+n]
__device__ unsigned g_Wll [64 * 64];          // Wl fp16 lo
__device__ float    g_q   [N_NODES * HD];
__device__ unsigned g_kh  [N_NODES * 64];     // k as half2 pairs
__device__ unsigned g_vh  [N_NODES * 64];     // v as half2 pairs
__device__ float    g_skip[N_NODES * HD];
__device__ unsigned g_fh  [N_NODES * 64];     // feat fp16 pairs
__device__ int   g_cnt [N_NODES];             // zero at load; re-zeroed by scan_apply
__device__ int   g_start[N_NODES + 1];
__device__ int   g_cur [N_NODES];
__device__ int   g_sorted[E_EDGES];
__device__ int   g_bsum[SCAN_BLOCKS];

__device__ __forceinline__ unsigned pack_f16(float lo, float hi) {
    unsigned r;
    asm("cvt.rn.f16x2.f32 %0, %1, %2;" : "=r"(r) : "f"(hi), "f"(lo));
    return r;
}

__device__ __forceinline__ void mma_f16(float* d, const unsigned* a, const unsigned* b) {
    asm("mma.sync.aligned.m16n8k16.row.col.f32.f16.f16.f32 "
        "{%0,%1,%2,%3}, {%4,%5,%6,%7}, {%8,%9}, {%0,%1,%2,%3};"
        : "+f"(d[0]), "+f"(d[1]), "+f"(d[2]), "+f"(d[3])
        : "r"(a[0]), "r"(a[1]), "r"(a[2]), "r"(a[3]), "r"(b[0]), "r"(b[1]));
}

// ---------------- K0 fused: x_y split + W split + Wl split + dst histogram ---
// blocks: [0,5000) xy | [5000,5128) Wqkvs | [5128,5144) Wl | [5144,7644) hist
// g_cnt is all-zero at entry (load-time zero-init; reset by k_scan_apply).
__global__ void __launch_bounds__(256)
k_init(const float* __restrict__ x, const int* __restrict__ y,
       const float* __restrict__ emb,
       const float* __restrict__ Wq, const float* __restrict__ Wk,
       const float* __restrict__ Wv, const float* __restrict__ Ws,
       const float* __restrict__ Wl, const int* __restrict__ ei) {
    int b = blockIdx.x;
    int tid = threadIdx.x;
    if (b < 5000) {
        int i = b * 256 + tid;                 // float4 index, exactly N*32
        int n  = i >> 5;
        int f4 = i & 31;
        int yv = y[n];
        float4 xv = ((const float4*)x)[i];
        float4 ev = *((const float4*)(emb + yv * F) + f4);
        unsigned h0 = pack_f16(xv.x + ev.x, xv.y + ev.y);
        unsigned h1 = pack_f16(xv.z + ev.z, xv.w + ev.w);
        ((uint2*)g_xh)[i] = make_uint2(h0, h1);
    } else if (b < 5128) {
        int i = (b - 5000) * 256 + tid;        // 4*64*128 = 32768 exactly
        int w   = i >> 13;
        int rem = i & 8191;
        int kp  = rem >> 7;
        int n   = rem & 127;
        const float* W = (w == 0) ? Wq : (w == 1) ? Wk : (w == 2) ? Wv : Ws;
        g_Wh[i] = pack_f16(W[(2 * kp) * 128 + n], W[(2 * kp + 1) * 128 + n]);
    } else if (b < 5144) {
        int i = (b - 5128) * 256 + tid;        // 64*64 = 4096 exactly
        int kp = i >> 6;
        int n  = i & 63;
        float w0 = Wl[(2 * kp)     * 64 + n];
        float w1 = Wl[(2 * kp + 1) * 64 + n];
        float h0 = __half2float(__float2half_rn(w0));
        float h1 = __half2float(__float2half_rn(w1));
        g_Wlh[i] = pack_f16(h0, h1);
        g_Wll[i] = pack_f16(w0 - h0, w1 - h1);
    } else {
        int i = (b - 5144) * 256 + tid;
        if (i < E_EDGES) atomicAdd(&g_cnt[ei[E_EDGES + i]], 1);
    }
}

// ---------------- CSR scan A: per-block inclusive scan + block sums ----------
__global__ void __launch_bounds__(256)
k_scan_local() {
    __shared__ int ps[256];
    int tid = threadIdx.x;
    int i   = blockIdx.x * 256 + tid;
    int v = (i < N_NODES) ? g_cnt[i] : 0;
    ps[tid] = v;
    __syncthreads();
    #pragma unroll
    for (int d = 1; d < 256; d <<= 1) {
        int t = (tid >= d) ? ps[tid - d] : 0;
        __syncthreads();
        ps[tid] += t;
        __syncthreads();
    }
    if (i < N_NODES) g_start[i] = ps[tid];
    if (tid == 255) g_bsum[blockIdx.x] = ps[255];
}

// ---------------- CSR scan B: apply + reset g_cnt for next invocation --------
__global__ void __launch_bounds__(256)
k_scan_apply() {
    __shared__ int bs[256];
    int tid = threadIdx.x;
    int v = (tid < SCAN_BLOCKS) ? g_bsum[tid] : 0;
    bs[tid] = v;
    __syncthreads();
    #pragma unroll
    for (int d = 1; d < 256; d <<= 1) {
        int t = (tid >= d) ? bs[tid - d] : 0;
        __syncthreads();
        bs[tid] += t;
        __syncthreads();
    }
    int off = (blockIdx.x == 0) ? 0 : bs[blockIdx.x - 1];
    int i = blockIdx.x * 256 + tid;
    if (i >= N_NODES) return;
    int ex = g_start[i] - g_cnt[i] + off;
    g_start[i] = ex;
    g_cur[i]   = ex;
    g_cnt[i]   = 0;                    // restore invariant for next launch/replay
    if (i == 0) g_start[N_NODES] = E_EDGES;
}

// ---------------- K1: projection GEMM (blocks < 313) + edge scatter (rest) ---
__global__ void __launch_bounds__(256, 2)
k_proj(const float* __restrict__ bq, const float* __restrict__ bk,
       const float* __restrict__ bv, const float* __restrict__ bs,
       const int* __restrict__ ei) {
    if (blockIdx.x >= PROJ_BLOCKS) {
        // ---- scatter branch: group src by dst ----
        int i = (blockIdx.x - PROJ_BLOCKS) * 256 + threadIdx.x;
        if (i < E_EDGES) {
            int src = ei[i];
            int dst = ei[E_EDGES + i];
            int pos = atomicAdd(&g_cur[dst], 1);
            g_sorted[pos] = src;
        }
        return;
    }
    __shared__ unsigned Ah[128 * ASTR];      // fp16 pairs, full K
    __shared__ unsigned Bh[2][1152];

    int tid  = threadIdx.x;
    int wid  = tid >> 5, lane = tid & 31;
    int wm   = wid >> 1;
    int wn   = wid & 1;
    int g    = lane >> 2;
    int tig  = lane & 3;
    int m0   = blockIdx.x * 128;

    #pragma unroll
    for (int t = 0; t < 32; t++) {
        int idx = tid + t * 256;
        int row = idx >> 6, kp = idx & 63;
        int gr  = m0 + row;
        Ah[row * ASTR + kp] = (gr < N_NODES) ? g_xh[gr * 64 + kp] : 0u;
    }
    #pragma unroll
    for (int t = 0; t < 4; t++) {
        int idx = tid + t * 256;
        int n = idx & 127, kp = idx >> 7;
        Bh[0][n * 9 + kp] = g_Wh[kp * 128 + n];
    }
    __syncthreads();

    for (int y = 0; y < 4; y++) {
        float C[2][8][4];
        #pragma unroll
        for (int mt = 0; mt < 2; mt++)
            #pragma unroll
            for (int nt = 0; nt < 8; nt++)
                #pragma unroll
                for (int c = 0; c < 4; c++) C[mt][nt][c] = 0.f;

        for (int ck = 0; ck < 8; ck++) {
            int it  = y * 8 + ck;
            int buf = it & 1;
            if (it < 31) {
                int nit = it + 1;
                int nbuf = buf ^ 1;
                const unsigned* Wh = g_Wh + (nit >> 3) * 8192 + (nit & 7) * 8 * 128;
                #pragma unroll
                for (int t = 0; t < 4; t++) {
                    int idx = tid + t * 256;
                    int n = idx & 127, kp = idx >> 7;
                    Bh[nbuf][n * 9 + kp] = Wh[kp * 128 + n];
                }
            }
            int ck8 = ck * 8;
            unsigned ah[2][4];
            #pragma unroll
            for (int mt = 0; mt < 2; mt++) {
                int base = wm * 32 + mt * 16;
                ah[mt][0] = Ah[(base + g)     * ASTR + ck8 + tig];
                ah[mt][1] = Ah[(base + g + 8) * ASTR + ck8 + tig];
                ah[mt][2] = Ah[(base + g)     * ASTR + ck8 + tig + 4];
                ah[mt][3] = Ah[(base + g + 8) * ASTR + ck8 + tig + 4];
            }
            #pragma unroll
            for (int nt = 0; nt < 8; nt++) {
                int nb = wn * 64 + nt * 8;
                unsigned bh2[2] = { Bh[buf][(nb + g) * 9 + tig], Bh[buf][(nb + g) * 9 + tig + 4] };
                #pragma unroll
                for (int mt = 0; mt < 2; mt++)
                    mma_f16(C[mt][nt], ah[mt], bh2);
            }
            __syncthreads();
        }

        const float* bias = (y == 0) ? bq : (y == 1) ? bk : (y == 2) ? bv : bs;
        #pragma unroll
        for (int nt = 0; nt < 8; nt++) {
            int col = wn * 64 + nt * 8 + 2 * tig;
            float2 b2 = *(const float2*)(bias + col);
            #pragma unroll
            for (int mt = 0; mt < 2; mt++) {
                int r0 = m0 + wm * 32 + mt * 16 + g;
                int r1 = r0 + 8;
                float v00 = C[mt][nt][0] + b2.x, v01 = C[mt][nt][1] + b2.y;
                float v10 = C[mt][nt][2] + b2.x, v11 = C[mt][nt][3] + b2.y;
                if (y == 1 || y == 2) {
                    unsigned* outp = (y == 1) ? g_kh : g_vh;
                    if (r0 < N_NODES) outp[r0 * 64 + (col >> 1)] = pack_f16(v00, v01);
                    if (r1 < N_NODES) outp[r1 * 64 + (col >> 1)] = pack_f16(v10, v11);
                } else {
                    float* outp = (y == 0) ? g_q : g_skip;
                    if (r0 < N_NODES) *(float2*)(outp + r0 * 128 + col) = make_float2(v00, v01);
                    if (r1 < N_NODES) *(float2*)(outp + r1 * 128 + col) = make_float2(v10, v11);
                }
            }
        }
    }
}

// ---------------- K2: CSR aggregation, 2 nodes per warp; feat -> fp16 --------
__global__ void __launch_bounds__(256)
k_agg(void) {
    int warp = blockIdx.x * 8 + (threadIdx.x >> 5);
    int lane = threadIdx.x & 31;
    int half = lane >> 4;
    int gl   = lane & 15;
    int n = warp * 2 + half;
    if (n >= N_NODES) return;
    int s0 = g_start[n];
    int s1 = g_start[n + 1];

    float q[8];
    *(float4*)(q)     = *(const float4*)(g_q + n * 128 + gl * 8);
    *(float4*)(q + 4) = *(const float4*)(g_q + n * 128 + gl * 8 + 4);

    float acc[8] = {0.f, 0.f, 0.f, 0.f, 0.f, 0.f, 0.f, 0.f};
    float den = 0.f;

    #define AGG_STEP(kc, vc) do {                                              \
        float2 kk0 = __half22float2(*(const __half2*)&(kc).x);                 \
        float2 kk1 = __half22float2(*(const __half2*)&(kc).y);                 \
        float2 kk2 = __half22float2(*(const __half2*)&(kc).z);                 \
        float2 kk3 = __half22float2(*(const __half2*)&(kc).w);                 \
        float sd = q[0]*kk0.x + q[1]*kk0.y + q[2]*kk1.x + q[3]*kk1.y           \
                 + q[4]*kk2.x + q[5]*kk2.y + q[6]*kk3.x + q[7]*kk3.y;          \
        sd += __shfl_xor_sync(0xffffffffu, sd, 1);                             \
        sd += __shfl_xor_sync(0xffffffffu, sd, 2);                             \
        float ea = __expf(sd * 0.17677669529663687f);                          \
        den += ea;                                                             \
        float2 vv0 = __half22float2(*(const __half2*)&(vc).x);                 \
        float2 vv1 = __half22float2(*(const __half2*)&(vc).y);                 \
        float2 vv2 = __half22float2(*(const __half2*)&(vc).z);                 \
        float2 vv3 = __half22float2(*(const __half2*)&(vc).w);                 \
        acc[0] = fmaf(ea, vv0.x, acc[0]);                                      \
        acc[1] = fmaf(ea, vv0.y, acc[1]);                                      \
        acc[2] = fmaf(ea, vv1.x, acc[2]);                                      \
        acc[3] = fmaf(ea, vv1.y, acc[3]);                                      \
        acc[4] = fmaf(ea, vv2.x, acc[4]);                                      \
        acc[5] = fmaf(ea, vv2.y, acc[5]);                                      \
        acc[6] = fmaf(ea, vv3.x, acc[6]);                                      \
        acc[7] = fmaf(ea, vv3.y, acc[7]);                                      \
    } while (0)

    int e = s0;
    if (s1 - s0 >= 2) {
        int sA = g_sorted[e], sB = g_sorted[e + 1];
        uint4 kA = *(const uint4*)(g_kh + sA * 64 + gl * 4);
        uint4 vA = *(const uint4*)(g_vh + sA * 64 + gl * 4);
        uint4 kB = *(const uint4*)(g_kh + sB * 64 + gl * 4);
        uint4 vB = *(const uint4*)(g_vh + sB * 64 + gl * 4);
        e += 2;
        while (e + 1 < s1) {
            int sC = g_sorted[e], sD = g_sorted[e + 1];
            uint4 kC = *(const uint4*)(g_kh + sC * 64 + gl * 4);
            uint4 vC = *(const uint4*)(g_vh + sC * 64 + gl * 4);
            uint4 kD = *(const uint4*)(g_kh + sD * 64 + gl * 4);
            uint4 vD = *(const uint4*)(g_vh + sD * 64 + gl * 4);
            AGG_STEP(kA, vA);
            AGG_STEP(kB, vB);
            kA = kC; vA = vC; kB = kD; vB = vD;
            e += 2;
        }
        AGG_STEP(kA, vA);
        AGG_STEP(kB, vB);
    }
    if (e < s1) {
        int s = g_sorted[e];
        uint4 kc = *(const uint4*)(g_kh + s * 64 + gl * 4);
        uint4 vc = *(const uint4*)(g_vh + s * 64 + gl * 4);
        AGG_STEP(kc, vc);
    }

    float inv = (den > 0.f) ? (1.0f / den) : 0.f;
    float4 s0f = *(const float4*)(g_skip + n * 128 + gl * 8);
    float4 s1f = *(const float4*)(g_skip + n * 128 + gl * 8 + 4);
    unsigned fh[4];
    fh[0] = pack_f16(fmaf(acc[0], inv, s0f.x), fmaf(acc[1], inv, s0f.y));
    fh[1] = pack_f16(fmaf(acc[2], inv, s0f.z), fmaf(acc[3], inv, s0f.w));
    fh[2] = pack_f16(fmaf(acc[4], inv, s1f.x), fmaf(acc[5], inv, s1f.y));
    fh[3] = pack_f16(fmaf(acc[6], inv, s1f.z), fmaf(acc[7], inv, s1f.w));
    *(uint4*)(g_fh + n * 64 + gl * 4) = make_uint4(fh[0], fh[1], fh[2], fh[3]);
}

// ---------------- K3: classifier, fp16 2-term MMA ----------------
__global__ void __launch_bounds__(256, 2)
k_cls(const float* __restrict__ bl, float* __restrict__ out) {
    __shared__ unsigned Ah[128 * 9];
    __shared__ unsigned Bh[64 * 9], Bl2[64 * 9];
    int tid  = threadIdx.x;
    int wid  = tid >> 5, lane = tid & 31;
    int wm   = wid >> 1;
    int wn   = wid & 1;
    int g    = lane >> 2;
    int tig  = lane & 3;
    int m0   = blockIdx.x * 128;

    float C[2][4][4];
    #pragma unroll
    for (int mt = 0; mt < 2; mt++)
        #pragma unroll
        for (int nt = 0; nt < 4; nt++)
            #pragma unroll
            for (int c = 0; c < 4; c++) C[mt][nt][c] = 0.f;

    for (int ck = 0; ck < 8; ck++) {
        __syncthreads();
        #pragma unroll
        for (int t = 0; t < 4; t++) {
            int idx = tid + t * 256;
            int row = idx >> 3, kp = idx & 7;
            int gr  = m0 + row;
            Ah[row * 9 + kp] = (gr < N_NODES) ? g_fh[gr * 64 + ck * 8 + kp] : 0u;
        }
        #pragma unroll
        for (int t = 0; t < 2; t++) {
            int idx = tid + t * 256;
            int n = idx & 63, kp = idx >> 6;
            Bh[n * 9 + kp]  = g_Wlh[(ck * 8 + kp) * 64 + n];
            Bl2[n * 9 + kp] = g_Wll[(ck * 8 + kp) * 64 + n];
        }
        __syncthreads();

        unsigned ah[2][4];
        #pragma unroll
        for (int mt = 0; mt < 2; mt++) {
            int base = wm * 32 + mt * 16;
            ah[mt][0] = Ah[(base + g)     * 9 + tig];
            ah[mt][1] = Ah[(base + g + 8) * 9 + tig];
            ah[mt][2] = Ah[(base + g)     * 9 + tig + 4];
            ah[mt][3] = Ah[(base + g + 8) * 9 + tig + 4];
        }
        #pragma unroll
        for (int nt = 0; nt < 4; nt++) {
            int nb = wn * 32 + nt * 8;
            unsigned bh2[2] = { Bh[(nb + g) * 9 + tig],  Bh[(nb + g) * 9 + tig + 4] };
            unsigned bl2[2] = { Bl2[(nb + g) * 9 + tig], Bl2[(nb + g) * 9 + tig + 4] };
            #pragma unroll
            for (int mt = 0; mt < 2; mt++) {
                mma_f16(C[mt][nt], ah[mt], bh2);
                mma_f16(C[mt][nt], ah[mt], bl2);
            }
        }
    }

    #pragma unroll
    for (int nt = 0; nt < 4; nt++) {
        int col = wn * 32 + nt * 8 + 2 * tig;
        float2 b2 = *(const float2*)(bl + col);
        #pragma unroll
        for (int mt = 0; mt < 2; mt++) {
            int r0 = m0 + wm * 32 + mt * 16 + g;
            int r1 = r0 + 8;
            if (r0 < N_NODES)
                *(float2*)(out + r0 * 64 + col) =
                    make_float2(C[mt][nt][0] + b2.x, C[mt][nt][1] + b2.y);
            if (r1 < N_NODES)
                *(float2*)(out + r1 * 64 + col) =
                    make_float2(C[mt][nt][2] + b2.x, C[mt][nt][3] + b2.y);
        }
    }
}

// ---------------- launch ----------------
extern "C" void kernel_launch(void* const* d_in, const int* in_sizes, int n_in,
                              void* d_out, int out_size) {
    const float* x   = (const float*)d_in[0];
    const int*   y   = (const int*)d_in[1];
    const int*   ei  = (const int*)d_in[2];
    const float* emb = (const float*)d_in[3];
    const float* Wq = (const float*)d_in[4];  const float* bq = (const float*)d_in[5];
    const float* Wk = (const float*)d_in[6];  const float* bk = (const float*)d_in[7];
    const float* Wv = (const float*)d_in[8];  const float* bv = (const float*)d_in[9];
    const float* Ws = (const float*)d_in[10]; const float* bs = (const float*)d_in[11];
    const float* Wl = (const float*)d_in[12]; const float* bl = (const float*)d_in[13];
    float* out = (float*)d_out;

    k_init      <<<5144 + EDGE_BLOCKS, 256>>>(x, y, emb, Wq, Wk, Wv, Ws, Wl, ei);
    k_scan_local<<<SCAN_BLOCKS, 256>>>();
    k_scan_apply<<<SCAN_BLOCKS, 256>>>();
    k_proj      <<<PROJ_BLOCKS + EDGE_BLOCKS, 256>>>(bq, bk, bv, bs, ei);
    k_agg       <<<(N_NODES / 2 + 7) / 8, 256>>>();
    k_cls       <<<(N_NODES + 127) / 128, 256>>>(bl, out);
}